// round 9
// baseline (speedup 1.0000x reference)
#include <cuda_runtime.h>
#include <cuda_bf16.h>
#include <cstdint>

typedef __nv_bfloat16 bf16;

#define EMBED 1024
#define TT 512
#define SS 512
#define BATCH 8
#define NHB 128
#define MROWS 4096

// ---------------- scratch (static device globals; no allocation allowed) ----
__device__ bf16 g_q_h[MROWS*EMBED],  g_q_l[MROWS*EMBED];
__device__ bf16 g_k_h[MROWS*EMBED],  g_k_l[MROWS*EMBED];
__device__ bf16 g_v_h[MROWS*EMBED],  g_v_l[MROWS*EMBED];
__device__ bf16 g_Wq_h[EMBED*EMBED], g_Wq_l[EMBED*EMBED];
__device__ bf16 g_Wk_h[EMBED*EMBED], g_Wk_l[EMBED*EMBED];
__device__ bf16 g_Wv_h[EMBED*EMBED], g_Wv_l[EMBED*EMBED];
__device__ bf16 g_Wo_h[EMBED*EMBED], g_Wo_l[EMBED*EMBED];
__device__ bf16 g_qp_h [NHB*TT*64],  g_qp_l [NHB*TT*64];   // [n][t][d]
__device__ bf16 g_kpT_h[NHB*64*SS],  g_kpT_l[NHB*64*SS];   // [n][d][s]
__device__ bf16 g_vp_h [NHB*SS*64],  g_vp_l [NHB*SS*64];   // [n][s][d]
__device__ float g_p [NHB*TT*SS];                          // p_choose (fp32)
__device__ bf16 g_al_h[NHB*TT*SS],   g_al_l[NHB*TT*SS];    // alpha [n][t][s]
__device__ bf16 g_at_h[MROWS*EMBED], g_at_l[MROWS*EMBED];  // merged [t*8+b][h*64+d]

// ============================================================================
// PTX helpers
// ============================================================================
__device__ __forceinline__ uint32_t smem_u32(const void* p) {
    uint32_t a;
    asm("{ .reg .u64 t; cvta.to.shared.u64 t, %1; cvt.u32.u64 %0, t; }"
        : "=r"(a) : "l"(p));
    return a;
}
__device__ __forceinline__ void ldmA(uint32_t r[4], uint32_t addr) {
    asm volatile("ldmatrix.sync.aligned.m8n8.x4.shared.b16 {%0,%1,%2,%3},[%4];"
        : "=r"(r[0]), "=r"(r[1]), "=r"(r[2]), "=r"(r[3]) : "r"(addr));
}
__device__ __forceinline__ void ldmBT(uint32_t r[4], uint32_t addr) {
    asm volatile("ldmatrix.sync.aligned.m8n8.x4.trans.shared.b16 {%0,%1,%2,%3},[%4];"
        : "=r"(r[0]), "=r"(r[1]), "=r"(r[2]), "=r"(r[3]) : "r"(addr));
}
__device__ __forceinline__ void mma16816(float c[4], const uint32_t a[4],
                                         uint32_t b0, uint32_t b1) {
    asm volatile(
        "mma.sync.aligned.m16n8k16.row.col.f32.bf16.bf16.f32 "
        "{%0,%1,%2,%3},{%4,%5,%6,%7},{%8,%9},{%0,%1,%2,%3};"
        : "+f"(c[0]), "+f"(c[1]), "+f"(c[2]), "+f"(c[3])
        : "r"(a[0]), "r"(a[1]), "r"(a[2]), "r"(a[3]), "r"(b0), "r"(b1));
}
__device__ __forceinline__ void cp16(uint32_t dst, const void* src) {
    asm volatile("cp.async.ca.shared.global [%0], [%1], 16;"
        :: "r"(dst), "l"(src));
}
__device__ __forceinline__ void cp_commit() {
    asm volatile("cp.async.commit_group;");
}
template<int N>
__device__ __forceinline__ void cp_wait() {
    asm volatile("cp.async.wait_group %0;" :: "n"(N));
}
__device__ __forceinline__ bf16 tobf(float v) { return __float2bfloat16(v); }

// ============================================================================
// bf16x3 GEMM core (R6 config): 2-stage cp.async, static smem (2 CTA/SM),
// fragment reuse, precomputed shared addresses.
// acc += Ah*Bh + Ah*Bl + Al*Bh.   Al = Ah + loA elements, Bl = Bh + loB.
// Block = 128 x BN, 256 threads (8 warps, wm=wid&3, wn=wid>>2).
// ============================================================================
template<int BN>
__device__ __forceinline__ void gemm_core(
    const bf16* __restrict__ Ah, long loA, int lda,
    const bf16* __restrict__ Bh, long loB, int ldb,
    int K, float acc[2][BN/16][4])
{
    constexpr int NT = BN / 16;
    constexpr int BSTR = BN + 40;            // 20 banks mod 32 -> conflict-free
    constexpr int ASZ = 2 * 128 * 40;        // elements per stage (hi+lo)
    constexpr int BSZ = 2 * 32 * BSTR;
    constexpr uint32_t ALOb = 128 * 40 * 2;  // hi->lo byte offset within stage
    constexpr uint32_t BLOb = 32 * BSTR * 2;
    constexpr uint32_t ASTb = ASZ * 2;       // stage byte strides
    constexpr uint32_t BSTb = BSZ * 2;
    __shared__ bf16 sA[2 * ASZ];
    __shared__ bf16 sB[2 * BSZ];
    const int tid = threadIdx.x;
    const int lane = tid & 31, wid = tid >> 5;
    const int wm = wid & 3, wn = wid >> 2;
    const int nTiles = K / 32;
    const uint32_t sAu = smem_u32(sA), sBu = smem_u32(sB);

    const int aR = tid >> 2, aC = (tid & 3) * 8;
    const int aR2 = aR + 64;
    const bf16* srcA0 = Ah + aR * lda + aC;
    const bf16* srcA1 = Ah + aR2 * lda + aC;
    const uint32_t dA0 = sAu + (uint32_t)(aR * 40 + aC) * 2;
    const uint32_t dA1 = sAu + (uint32_t)(aR2 * 40 + aC) * 2;
    constexpr int BCH = (BN / 8) * 32 / 256;
    const bf16* srcB[BCH];
    uint32_t dB[BCH];
#pragma unroll
    for (int i = 0; i < BCH; i++) {
        int id = tid + i * 256;
        int rr = id / (BN / 8), cc = (id % (BN / 8)) * 8;
        srcB[i] = Bh + rr * ldb + cc;
        dB[i] = sBu + (uint32_t)(rr * BSTR + cc) * 2;
    }

    uint32_t bAddr[NT / 2];
#pragma unroll
    for (int np = 0; np < NT / 2; np++)
        bAddr[np] = sBu + (uint32_t)((lane & 15) * BSTR +
                     wn * (NT * 8) + np * 16 + ((lane >> 4) << 3)) * 2;
    uint32_t aAddr[2];
#pragma unroll
    for (int mt = 0; mt < 2; mt++)
        aAddr[mt] = sAu + (uint32_t)((wm * 32 + mt * 16 + (lane & 15)) * 40 +
                     ((lane >> 4) << 3)) * 2;

    auto loadTile = [&](uint32_t stA, uint32_t stB) {
        cp16(dA0 + stA, srcA0);  cp16(dA0 + ALOb + stA, srcA0 + loA);
        cp16(dA1 + stA, srcA1);  cp16(dA1 + ALOb + stA, srcA1 + loA);
        srcA0 += 32; srcA1 += 32;
#pragma unroll
        for (int i = 0; i < BCH; i++) {
            cp16(dB[i] + stB, srcB[i]);
            cp16(dB[i] + BLOb + stB, srcB[i] + loB);
            srcB[i] += 32 * ldb;
        }
    };

    loadTile(0, 0);
    cp_commit();

    for (int i = 0; i < nTiles; i++) {
        if (i + 1 < nTiles) {
            loadTile(((i + 1) & 1) ? ASTb : 0u, ((i + 1) & 1) ? BSTb : 0u);
            cp_commit();
            cp_wait<1>();
        } else {
            cp_wait<0>();
        }
        __syncthreads();

        const uint32_t stA = (i & 1) ? ASTb : 0u;
        const uint32_t stB = (i & 1) ? BSTb : 0u;
#pragma unroll
        for (int kk = 0; kk < 2; kk++) {
            const uint32_t kA = stA + (kk ? 32u : 0u);
            const uint32_t kB = stB + (kk ? 16u * BSTR * 2u : 0u);
            uint32_t bh[NT][2];
#pragma unroll
            for (int np = 0; np < NT / 2; np++) {
                uint32_t rr[4];
                ldmBT(rr, bAddr[np] + kB);
                bh[2 * np][0] = rr[0]; bh[2 * np][1] = rr[1];
                bh[2 * np + 1][0] = rr[2]; bh[2 * np + 1][1] = rr[3];
            }
            uint32_t ah[2][4], al[2][4];
#pragma unroll
            for (int mt = 0; mt < 2; mt++) {
                ldmA(ah[mt], aAddr[mt] + kA);
                ldmA(al[mt], aAddr[mt] + ALOb + kA);
            }
#pragma unroll
            for (int mt = 0; mt < 2; mt++)
#pragma unroll
                for (int nt = 0; nt < NT; nt++) {
                    mma16816(acc[mt][nt], ah[mt], bh[nt][0], bh[nt][1]);
                    mma16816(acc[mt][nt], al[mt], bh[nt][0], bh[nt][1]);
                }
#pragma unroll
            for (int np = 0; np < NT / 2; np++) {
                uint32_t rr[4];
                ldmBT(rr, bAddr[np] + BLOb + kB);
#pragma unroll
                for (int mt = 0; mt < 2; mt++) {
                    mma16816(acc[mt][2 * np],     ah[mt], rr[0], rr[1]);
                    mma16816(acc[mt][2 * np + 1], ah[mt], rr[2], rr[3]);
                }
            }
        }
        __syncthreads();
    }
}

#define EPI_ROW(mt, r)     (wm * 32 + (mt) * 16 + (lane >> 2) + (((r) >> 1) << 3))
#define EPI_COL(nt, r, NT) (wn * ((NT) * 8) + (nt) * 8 + ((lane & 3) << 1) + ((r) & 1))

// ============================================================================
// split kernels: fp32 -> (bf16 hi, bf16 lo). blockIdx.y selects tensor.
// ============================================================================
__global__ void split_act_kernel(const float* __restrict__ q,
                                 const float* __restrict__ k,
                                 const float* __restrict__ v)
{
    const float* x; bf16 *h, *l;
    switch (blockIdx.y) {
        case 0:  x = q; h = g_q_h; l = g_q_l; break;
        case 1:  x = k; h = g_k_h; l = g_k_l; break;
        default: x = v; h = g_v_h; l = g_v_l; break;
    }
    int i = blockIdx.x * blockDim.x + threadIdx.x;
    float val = x[i];
    bf16 hv = tobf(val);
    h[i] = hv;
    l[i] = tobf(val - __bfloat162float(hv));
}

__global__ void split_w_kernel(const float* __restrict__ Wq,
                               const float* __restrict__ Wk,
                               const float* __restrict__ Wv,
                               const float* __restrict__ Wo)
{
    const float* x; bf16 *h, *l;
    switch (blockIdx.y) {
        case 0:  x = Wq; h = g_Wq_h; l = g_Wq_l; break;
        case 1:  x = Wk; h = g_Wk_h; l = g_Wk_l; break;
        case 2:  x = Wv; h = g_Wv_h; l = g_Wv_l; break;
        default: x = Wo; h = g_Wo_h; l = g_Wo_l; break;
    }
    int i = blockIdx.x * blockDim.x + threadIdx.x;
    float val = x[i];
    bf16 hv = tobf(val);
    h[i] = hv;
    l[i] = tobf(val - __bfloat162float(hv));
}

// ============================================================================
// Merged projection GEMM: blockIdx.z = which (0=Q,1=K,2=V).
// ============================================================================
__global__ __launch_bounds__(256, 2) void proj_mma_kernel()
{
    const int which = blockIdx.z;
    const bf16 *Ah, *Wh;
    long loA, loW;
    if (which == 0)      { Ah = g_q_h; loA = g_q_l - g_q_h; Wh = g_Wq_h; loW = g_Wq_l - g_Wq_h; }
    else if (which == 1) { Ah = g_k_h; loA = g_k_l - g_k_h; Wh = g_Wk_h; loW = g_Wk_l - g_Wk_h; }
    else                 { Ah = g_v_h; loA = g_v_l - g_v_h; Wh = g_Wv_h; loW = g_Wv_l - g_Wv_h; }
    const float scale = (which == 0) ? 0.125f : 1.0f;

    const int bm = blockIdx.y * 128, bn = blockIdx.x * 128;
    float acc[2][8][4];
#pragma unroll
    for (int i = 0; i < 2; i++)
#pragma unroll
        for (int j = 0; j < 8; j++)
#pragma unroll
            for (int r = 0; r < 4; r++) acc[i][j][r] = 0.f;

    gemm_core<128>(Ah + bm * 1024, loA, 1024, Wh + bn, loW, 1024, 1024, acc);

    const int lane = threadIdx.x & 31, wid = threadIdx.x >> 5;
    const int wm = wid & 3, wn = wid >> 2;
    bf16 *dh, *dl;
    if (which == 0)      { dh = g_qp_h;  dl = g_qp_l;  }
    else if (which == 1) { dh = g_kpT_h; dl = g_kpT_l; }
    else                 { dh = g_vp_h;  dl = g_vp_l;  }

    if (which == 1) {
#pragma unroll
        for (int mt = 0; mt < 2; mt++)
#pragma unroll
            for (int nt = 0; nt < 8; nt++)
#pragma unroll
                for (int r = 0; r < 4; r++) {
                    int row = bm + EPI_ROW(mt, r);
                    int col = bn + EPI_COL(nt, r, 8);
                    int t = row >> 3, b = row & 7;
                    int h = col >> 6, d = col & 63;
                    int n = b * 16 + h;
                    float v = acc[mt][nt][r];
                    int idx = (n * 64 + d) * 512 + t;
                    bf16 hv = tobf(v);
                    dh[idx] = hv;
                    dl[idx] = tobf(v - __bfloat162float(hv));
                }
    } else {
#pragma unroll
        for (int mt = 0; mt < 2; mt++)
#pragma unroll
            for (int nt = 0; nt < 8; nt++)
#pragma unroll
                for (int r2 = 0; r2 < 4; r2 += 2) {
                    int row = bm + EPI_ROW(mt, r2);
                    int col = bn + EPI_COL(nt, r2, 8);   // even
                    int t = row >> 3, b = row & 7;
                    int h = col >> 6, d = col & 63;
                    int n = b * 16 + h;
                    int idx = (n * 512 + t) * 64 + d;
                    float v0 = acc[mt][nt][r2] * scale;
                    float v1 = acc[mt][nt][r2 + 1] * scale;
                    bf16 h0 = tobf(v0), h1 = tobf(v1);
                    __nv_bfloat162 hp; hp.x = h0; hp.y = h1;
                    __nv_bfloat162 lp;
                    lp.x = tobf(v0 - __bfloat162float(h0));
                    lp.y = tobf(v1 - __bfloat162float(h1));
                    *(__nv_bfloat162*)&dh[idx] = hp;
                    *(__nv_bfloat162*)&dl[idx] = lp;
                }
    }
}

// ============================================================================
// Energy + sigmoid -> g_p (fp32)
// ============================================================================
__global__ __launch_bounds__(256, 2) void energy_mma_kernel(const float* __restrict__ ebias)
{
    const int n = blockIdx.z;
    const int t0 = blockIdx.y * 128, s0 = blockIdx.x * 128;
    float acc[2][8][4];
#pragma unroll
    for (int i = 0; i < 2; i++)
#pragma unroll
        for (int j = 0; j < 8; j++)
#pragma unroll
            for (int r = 0; r < 4; r++) acc[i][j][r] = 0.f;

    gemm_core<128>(g_qp_h + n * 512 * 64 + t0 * 64, g_qp_l - g_qp_h, 64,
                   g_kpT_h + n * 64 * 512 + s0,     g_kpT_l - g_kpT_h, 512,
                   64, acc);

    const int lane = threadIdx.x & 31, wid = threadIdx.x >> 5;
    const int wm = wid & 3, wn = wid >> 2;
    const float eb = ebias[0];
#pragma unroll
    for (int mt = 0; mt < 2; mt++)
#pragma unroll
        for (int nt = 0; nt < 8; nt++)
#pragma unroll
            for (int r2 = 0; r2 < 4; r2 += 2) {
                int t = t0 + EPI_ROW(mt, r2);
                int s = s0 + EPI_COL(nt, r2, 8);
                float e0 = acc[mt][nt][r2] + eb;
                float e1 = acc[mt][nt][r2 + 1] + eb;
                float2 pv;
                pv.x = 1.f / (1.f + __expf(-e0));
                pv.y = 1.f / (1.f + __expf(-e1));
                *(float2*)&g_p[(n * 512 + t) * 512 + s] = pv;
            }
}

// ============================================================================
// Fused recurrence — 128 threads x 4 s-elements, ONE barrier per t-step.
// Exclusive cumprod of (1-p) for row t+1 and the alpha sum-scan for row t
// share one interleaved shfl chain.  Mass-preservation write of row t's
// last column is deferred to step t+1 (double-buffered warp-total arrays).
// One block per n (128 blocks).
// ============================================================================
__global__ __launch_bounds__(128) void recurrence_kernel()
{
    const int tid = threadIdx.x;          // 0..127, covers s = 4*tid..4*tid+3
    const int n = blockIdx.x;
    const int lane = tid & 31, wid = tid >> 5;
    const long base = (long)n * (512 * 512) + tid * 4;

    __shared__ float sh_sw[2][4], sh_pw[2][4], sh_m[2][4];

    float cl[4], pc[4];
    // ---- prologue: exclusive cumprod of (1-p) for row 0 ----
    {
        float4 p4 = *(const float4*)&g_p[base];
        float pr[4] = {p4.x, p4.y, p4.z, p4.w};
        float lp[4];
        lp[0] = 1.f - pr[0];
        lp[1] = lp[0] * (1.f - pr[1]);
        lp[2] = lp[1] * (1.f - pr[2]);
        lp[3] = lp[2] * (1.f - pr[3]);
        float V = lp[3];
#pragma unroll
        for (int o = 1; o < 32; o <<= 1) {
            float vv = __shfl_up_sync(0xffffffffu, V, o);
            if (lane >= o) V *= vv;
        }
        float Vex = __shfl_up_sync(0xffffffffu, V, 1);
        if (lane == 0) Vex = 1.f;
        if (lane == 31) sh_pw[0][wid] = V;
        __syncthreads();
        float woffV = 1.f;
#pragma unroll
        for (int k2 = 0; k2 < 3; k2++)
            if (k2 < wid) woffV *= sh_pw[0][k2];
        float pbase = woffV * Vex;
        float ex[4];
        ex[0] = pbase;
        ex[1] = pbase * lp[0];
        ex[2] = pbase * lp[1];
        ex[3] = pbase * lp[2];
#pragma unroll
        for (int j = 0; j < 4; j++) {
            cl[j] = fminf(fmaxf(ex[j], 1e-6f), 1.f);
            pc[j] = pr[j] * ex[j];
        }
        __syncthreads();   // protect sh_pw[0] before t=0 re-writes it
    }

    float ap[4] = {0.f, 0.f, 0.f, 0.f};
    if (tid == 0) ap[0] = 1.f;

    for (int t = 0; t < 512; t++) {
        const int buf = t & 1;
        float pn[4];
        if (t < 511) {
            float4 p4 = *(const float4*)&g_p[base + (long)(t + 1) * 512];
            pn[0] = p4.x; pn[1] = p4.y; pn[2] = p4.z; pn[3] = p4.w;
        } else {
            pn[0] = pn[1] = pn[2] = pn[3] = 0.f;
        }

        // local prefix sums (aprev/cl) and prefix products (1-pnext)
        float u0 = ap[0] / cl[0], u1 = ap[1] / cl[1];
        float u2 = ap[2] / cl[2], u3 = ap[3] / cl[3];
        float ls[4];
        ls[0] = u0; ls[1] = ls[0] + u1; ls[2] = ls[1] + u2; ls[3] = ls[2] + u3;
        float lp[4];
        lp[0] = 1.f - pn[0];
        lp[1] = lp[0] * (1.f - pn[1]);
        lp[2] = lp[1] * (1.f - pn[2]);
        lp[3] = lp[2] * (1.f - pn[3]);

        // interleaved warp scans over thread totals
        float U = ls[3], V = lp[3];
#pragma unroll
        for (int o = 1; o < 32; o <<= 1) {
            float uu = __shfl_up_sync(0xffffffffu, U, o);
            float vv = __shfl_up_sync(0xffffffffu, V, o);
            if (lane >= o) { U += uu; V *= vv; }
        }
        float Uex = __shfl_up_sync(0xffffffffu, U, 1);
        float Vex = __shfl_up_sync(0xffffffffu, V, 1);
        if (lane == 0) { Uex = 0.f; Vex = 1.f; }
        if (lane == 31) { sh_sw[buf][wid] = U; sh_pw[buf][wid] = V; }
        __syncthreads();                             // the ONE barrier

        float woffU = 0.f, woffV = 1.f;
#pragma unroll
        for (int k2 = 0; k2 < 3; k2++)
            if (k2 < wid) { woffU += sh_sw[buf][k2]; woffV *= sh_pw[buf][k2]; }

        float sbase = woffU + Uex;
        float araw[4];
        araw[0] = fminf(fmaxf(pc[0] * (sbase + ls[0]), 0.f), 1.f);
        araw[1] = fminf(fmaxf(pc[1] * (sbase + ls[1]), 0.f), 1.f);
        araw[2] = fminf(fmaxf(pc[2] * (sbase + ls[2]), 0.f), 1.f);
        araw[3] = fminf(fmaxf(pc[3] * (sbase + ls[3]), 0.f), 1.f);

        // next-row exclusive cumprod -> cl/pc for step t+1
        {
            float pbase = woffV * Vex;
            float ex0 = pbase, ex1 = pbase * lp[0];
            float ex2 = pbase * lp[1], ex3 = pbase * lp[2];
            cl[0] = fminf(fmaxf(ex0, 1e-6f), 1.f);  pc[0] = pn[0] * ex0;
            cl[1] = fminf(fmaxf(ex1, 1e-6f), 1.f);  pc[1] = pn[1] * ex1;
            cl[2] = fminf(fmaxf(ex2, 1e-6f), 1.f);  pc[2] = pn[2] * ex2;
            cl[3] = fminf(fmaxf(ex3, 1e-6f), 1.f);  pc[3] = pn[3] * ex3;
        }

        // store alpha row t (raw; s=511 is overwritten next step by same thread)
        {
            __nv_bfloat162 h01, h23, l01, l23;
            h01.x = tobf(araw[0]); h01.y = tobf(araw[1]);
            h23.x = tobf(araw[2]); h23.y = tobf(araw[3]);
            l01.x = tobf(araw[0] - __bfloat162float(h01.x));
            l01.y = tobf(araw[1] - __bfloat162float(h01.y));
            l23.x = tobf(araw[2] - __bfloat162float(h23.x));
            l23.y = tobf(araw[3] - __bfloat162float(h23.y));
            uint2 H, L;
            H.x = *(uint32_t*)&h01; H.y = *(uint32_t*)&h23;
            L.x = *(uint32_t*)&l01; L.y = *(uint32_t*)&l23;
            *(uint2*)&g_al_h[base + (long)t * 512] = H;
            *(uint2*)&g_al_l[base + (long)t * 512] = L;
        }

        // mass reduction over clipped alpha (s < 511)
        float M = araw[0] + araw[1] + araw[2] + ((tid == 127) ? 0.f : araw[3]);
#pragma unroll
        for (int o = 16; o > 0; o >>= 1)
            M += __shfl_xor_sync(0xffffffffu, M, o);
        if (lane == 0) sh_m[buf][wid] = M;

        // deferred: fix row t-1's last column (sh_m[1-buf] was published by
        // this step's barrier)
        if (t > 0 && tid == 127) {
            float total = sh_m[1 - buf][0] + sh_m[1 - buf][1] +
                          sh_m[1 - buf][2] + sh_m[1 - buf][3];
            float aout = 1.f - fminf(fmaxf(total, 0.f), 1.f);
            bf16 hv = tobf(aout);
            g_al_h[base + (long)(t - 1) * 512 + 3] = hv;
            g_al_l[base + (long)(t - 1) * 512 + 3] = tobf(aout - __bfloat162float(hv));
        }

        ap[0] = araw[0]; ap[1] = araw[1]; ap[2] = araw[2]; ap[3] = araw[3];
    }

    // epilogue: row 511's last column (511 & 1 == 1)
    __syncthreads();
    if (tid == 127) {
        float total = sh_m[1][0] + sh_m[1][1] + sh_m[1][2] + sh_m[1][3];
        float aout = 1.f - fminf(fmaxf(total, 0.f), 1.f);
        bf16 hv = tobf(aout);
        g_al_h[base + 511L * 512 + 3] = hv;
        g_al_l[base + 511L * 512 + 3] = tobf(aout - __bfloat162float(hv));
    }
}

// ============================================================================
// attn = alpha @ vp  (per n: [512x512]@[512x64]) -> merged hi/lo.
// ============================================================================
__global__ __launch_bounds__(256, 2) void attnv_mma_kernel()
{
    const int n = blockIdx.z;
    const int t0 = blockIdx.y * 128;
    float acc[2][4][4];
#pragma unroll
    for (int i = 0; i < 2; i++)
#pragma unroll
        for (int j = 0; j < 4; j++)
#pragma unroll
            for (int r = 0; r < 4; r++) acc[i][j][r] = 0.f;

    gemm_core<64>(g_al_h + n * 512 * 512 + t0 * 512, g_al_l - g_al_h, 512,
                  g_vp_h + n * 512 * 64,             g_vp_l - g_vp_h, 64,
                  512, acc);

    const int lane = threadIdx.x & 31, wid = threadIdx.x >> 5;
    const int wm = wid & 3, wn = wid >> 2;
    const int b = n >> 4, h = n & 15;
#pragma unroll
    for (int mt = 0; mt < 2; mt++)
#pragma unroll
        for (int nt = 0; nt < 4; nt++)
#pragma unroll
            for (int r2 = 0; r2 < 4; r2 += 2) {
                int t = t0 + EPI_ROW(mt, r2);
                int d = EPI_COL(nt, r2, 4);
                int idx = (t * 8 + b) * 1024 + h * 64 + d;
                float v0 = acc[mt][nt][r2], v1 = acc[mt][nt][r2 + 1];
                bf16 h0 = tobf(v0), h1 = tobf(v1);
                __nv_bfloat162 hp; hp.x = h0; hp.y = h1;
                __nv_bfloat162 lp;
                lp.x = tobf(v0 - __bfloat162float(h0));
                lp.y = tobf(v1 - __bfloat162float(h1));
                *(__nv_bfloat162*)&g_at_h[idx] = hp;
                *(__nv_bfloat162*)&g_at_l[idx] = lp;
            }
}

// ============================================================================
// Output projection: out = attn[4096x1024] @ Wo + bo (fp32 out)
// ============================================================================
__global__ __launch_bounds__(256, 2) void out_mma_kernel(
    const float* __restrict__ bias, float* __restrict__ out)
{
    const int bm = blockIdx.y * 128, bn = blockIdx.x * 128;
    float acc[2][8][4];
#pragma unroll
    for (int i = 0; i < 2; i++)
#pragma unroll
        for (int j = 0; j < 8; j++)
#pragma unroll
            for (int r = 0; r < 4; r++) acc[i][j][r] = 0.f;

    gemm_core<128>(g_at_h + bm * 1024, g_at_l - g_at_h, 1024,
                   g_Wo_h + bn,        g_Wo_l - g_Wo_h, 1024, 1024, acc);

    const int lane = threadIdx.x & 31, wid = threadIdx.x >> 5;
    const int wm = wid & 3, wn = wid >> 2;
#pragma unroll
    for (int mt = 0; mt < 2; mt++)
#pragma unroll
        for (int nt = 0; nt < 8; nt++)
#pragma unroll
            for (int r2 = 0; r2 < 4; r2 += 2) {
                int row = bm + EPI_ROW(mt, r2);
                int col = bn + EPI_COL(nt, r2, 8);
                float2 ov;
                ov.x = acc[mt][nt][r2]     + bias[col];
                ov.y = acc[mt][nt][r2 + 1] + bias[col + 1];
                *(float2*)&out[row * 1024 + col] = ov;
            }
}

// ============================================================================
extern "C" void kernel_launch(void* const* d_in, const int* in_sizes, int n_in,
                              void* d_out, int out_size)
{
    const float* q  = (const float*)d_in[0];
    const float* k  = (const float*)d_in[1];
    const float* v  = (const float*)d_in[2];
    const float* Wq = (const float*)d_in[3];
    const float* Wk = (const float*)d_in[4];
    const float* Wv = (const float*)d_in[5];
    const float* Wo = (const float*)d_in[6];
    const float* bo = (const float*)d_in[7];
    const float* eb = (const float*)d_in[8];
    float* out = (float*)d_out;

    split_act_kernel<<<dim3(MROWS * EMBED / 256, 3), 256>>>(q, k, v);
    split_w_kernel<<<dim3(EMBED * EMBED / 256, 4), 256>>>(Wq, Wk, Wv, Wo);

    proj_mma_kernel<<<dim3(8, 32, 3), 256>>>();
    energy_mma_kernel<<<dim3(4, 4, 128), 256>>>(eb);
    recurrence_kernel<<<128, 128>>>();
    attnv_mma_kernel<<<dim3(1, 4, 128), 256>>>();
    out_mma_kernel<<<dim3(8, 32), 256>>>(bo, out);
}

// round 10
// speedup vs baseline: 1.1351x; 1.1351x over previous
#include <cuda_runtime.h>
#include <cuda_bf16.h>
#include <cstdint>

typedef __nv_bfloat16 bf16;

#define EMBED 1024
#define TT 512
#define SS 512
#define BATCH 8
#define NHB 128
#define MROWS 4096

// ---------------- scratch (static device globals; no allocation allowed) ----
__device__ bf16 g_q_h[MROWS*EMBED],  g_q_l[MROWS*EMBED];
__device__ bf16 g_k_h[MROWS*EMBED],  g_k_l[MROWS*EMBED];
__device__ bf16 g_v_h[MROWS*EMBED],  g_v_l[MROWS*EMBED];
__device__ bf16 g_Wq_h[EMBED*EMBED], g_Wq_l[EMBED*EMBED];
__device__ bf16 g_Wk_h[EMBED*EMBED], g_Wk_l[EMBED*EMBED];
__device__ bf16 g_Wv_h[EMBED*EMBED], g_Wv_l[EMBED*EMBED];
__device__ bf16 g_Wo_h[EMBED*EMBED], g_Wo_l[EMBED*EMBED];
__device__ bf16 g_qp_h [NHB*TT*64],  g_qp_l [NHB*TT*64];   // [n][t][d]
__device__ bf16 g_kpT_h[NHB*64*SS],  g_kpT_l[NHB*64*SS];   // [n][d][s]
__device__ bf16 g_vp_h [NHB*SS*64],  g_vp_l [NHB*SS*64];   // [n][s][d]
__device__ float g_p [NHB*TT*SS];                          // p_choose (fp32)
__device__ bf16 g_al_h[NHB*TT*SS],   g_al_l[NHB*TT*SS];    // alpha [n][t][s]
__device__ bf16 g_at_h[MROWS*EMBED], g_at_l[MROWS*EMBED];  // merged [t*8+b][h*64+d]

// ============================================================================
// PTX helpers
// ============================================================================
__device__ __forceinline__ uint32_t smem_u32(const void* p) {
    uint32_t a;
    asm("{ .reg .u64 t; cvta.to.shared.u64 t, %1; cvt.u32.u64 %0, t; }"
        : "=r"(a) : "l"(p));
    return a;
}
__device__ __forceinline__ void ldmA(uint32_t r[4], uint32_t addr) {
    asm volatile("ldmatrix.sync.aligned.m8n8.x4.shared.b16 {%0,%1,%2,%3},[%4];"
        : "=r"(r[0]), "=r"(r[1]), "=r"(r[2]), "=r"(r[3]) : "r"(addr));
}
__device__ __forceinline__ void ldmBT(uint32_t r[4], uint32_t addr) {
    asm volatile("ldmatrix.sync.aligned.m8n8.x4.trans.shared.b16 {%0,%1,%2,%3},[%4];"
        : "=r"(r[0]), "=r"(r[1]), "=r"(r[2]), "=r"(r[3]) : "r"(addr));
}
__device__ __forceinline__ void mma16816(float c[4], const uint32_t a[4],
                                         uint32_t b0, uint32_t b1) {
    asm volatile(
        "mma.sync.aligned.m16n8k16.row.col.f32.bf16.bf16.f32 "
        "{%0,%1,%2,%3},{%4,%5,%6,%7},{%8,%9},{%0,%1,%2,%3};"
        : "+f"(c[0]), "+f"(c[1]), "+f"(c[2]), "+f"(c[3])
        : "r"(a[0]), "r"(a[1]), "r"(a[2]), "r"(a[3]), "r"(b0), "r"(b1));
}
__device__ __forceinline__ void cp16(uint32_t dst, const void* src) {
    asm volatile("cp.async.ca.shared.global [%0], [%1], 16;"
        :: "r"(dst), "l"(src));
}
__device__ __forceinline__ void cp_commit() {
    asm volatile("cp.async.commit_group;");
}
template<int N>
__device__ __forceinline__ void cp_wait() {
    asm volatile("cp.async.wait_group %0;" :: "n"(N));
}
__device__ __forceinline__ bf16 tobf(float v) { return __float2bfloat16(v); }

// ============================================================================
// bf16x3 GEMM core (R6 config): 2-stage cp.async, static smem (2 CTA/SM),
// fragment reuse, precomputed shared addresses.
// acc += Ah*Bh + Ah*Bl + Al*Bh.   Al = Ah + loA elements, Bl = Bh + loB.
// Block = 128 x BN, 256 threads (8 warps, wm=wid&3, wn=wid>>2).
// ============================================================================
template<int BN>
__device__ __forceinline__ void gemm_core(
    const bf16* __restrict__ Ah, long loA, int lda,
    const bf16* __restrict__ Bh, long loB, int ldb,
    int K, float acc[2][BN/16][4])
{
    constexpr int NT = BN / 16;
    constexpr int BSTR = BN + 40;            // 20 banks mod 32 -> conflict-free
    constexpr int ASZ = 2 * 128 * 40;        // elements per stage (hi+lo)
    constexpr int BSZ = 2 * 32 * BSTR;
    constexpr uint32_t ALOb = 128 * 40 * 2;  // hi->lo byte offset within stage
    constexpr uint32_t BLOb = 32 * BSTR * 2;
    constexpr uint32_t ASTb = ASZ * 2;       // stage byte strides
    constexpr uint32_t BSTb = BSZ * 2;
    __shared__ bf16 sA[2 * ASZ];
    __shared__ bf16 sB[2 * BSZ];
    const int tid = threadIdx.x;
    const int lane = tid & 31, wid = tid >> 5;
    const int wm = wid & 3, wn = wid >> 2;
    const int nTiles = K / 32;
    const uint32_t sAu = smem_u32(sA), sBu = smem_u32(sB);

    const int aR = tid >> 2, aC = (tid & 3) * 8;
    const int aR2 = aR + 64;
    const bf16* srcA0 = Ah + aR * lda + aC;
    const bf16* srcA1 = Ah + aR2 * lda + aC;
    const uint32_t dA0 = sAu + (uint32_t)(aR * 40 + aC) * 2;
    const uint32_t dA1 = sAu + (uint32_t)(aR2 * 40 + aC) * 2;
    constexpr int BCH = (BN / 8) * 32 / 256;
    const bf16* srcB[BCH];
    uint32_t dB[BCH];
#pragma unroll
    for (int i = 0; i < BCH; i++) {
        int id = tid + i * 256;
        int rr = id / (BN / 8), cc = (id % (BN / 8)) * 8;
        srcB[i] = Bh + rr * ldb + cc;
        dB[i] = sBu + (uint32_t)(rr * BSTR + cc) * 2;
    }

    uint32_t bAddr[NT / 2];
#pragma unroll
    for (int np = 0; np < NT / 2; np++)
        bAddr[np] = sBu + (uint32_t)((lane & 15) * BSTR +
                     wn * (NT * 8) + np * 16 + ((lane >> 4) << 3)) * 2;
    uint32_t aAddr[2];
#pragma unroll
    for (int mt = 0; mt < 2; mt++)
        aAddr[mt] = sAu + (uint32_t)((wm * 32 + mt * 16 + (lane & 15)) * 40 +
                     ((lane >> 4) << 3)) * 2;

    auto loadTile = [&](uint32_t stA, uint32_t stB) {
        cp16(dA0 + stA, srcA0);  cp16(dA0 + ALOb + stA, srcA0 + loA);
        cp16(dA1 + stA, srcA1);  cp16(dA1 + ALOb + stA, srcA1 + loA);
        srcA0 += 32; srcA1 += 32;
#pragma unroll
        for (int i = 0; i < BCH; i++) {
            cp16(dB[i] + stB, srcB[i]);
            cp16(dB[i] + BLOb + stB, srcB[i] + loB);
            srcB[i] += 32 * ldb;
        }
    };

    loadTile(0, 0);
    cp_commit();

    for (int i = 0; i < nTiles; i++) {
        if (i + 1 < nTiles) {
            loadTile(((i + 1) & 1) ? ASTb : 0u, ((i + 1) & 1) ? BSTb : 0u);
            cp_commit();
            cp_wait<1>();
        } else {
            cp_wait<0>();
        }
        __syncthreads();

        const uint32_t stA = (i & 1) ? ASTb : 0u;
        const uint32_t stB = (i & 1) ? BSTb : 0u;
#pragma unroll
        for (int kk = 0; kk < 2; kk++) {
            const uint32_t kA = stA + (kk ? 32u : 0u);
            const uint32_t kB = stB + (kk ? 16u * BSTR * 2u : 0u);
            uint32_t bh[NT][2];
#pragma unroll
            for (int np = 0; np < NT / 2; np++) {
                uint32_t rr[4];
                ldmBT(rr, bAddr[np] + kB);
                bh[2 * np][0] = rr[0]; bh[2 * np][1] = rr[1];
                bh[2 * np + 1][0] = rr[2]; bh[2 * np + 1][1] = rr[3];
            }
            uint32_t ah[2][4], al[2][4];
#pragma unroll
            for (int mt = 0; mt < 2; mt++) {
                ldmA(ah[mt], aAddr[mt] + kA);
                ldmA(al[mt], aAddr[mt] + ALOb + kA);
            }
#pragma unroll
            for (int mt = 0; mt < 2; mt++)
#pragma unroll
                for (int nt = 0; nt < NT; nt++) {
                    mma16816(acc[mt][nt], ah[mt], bh[nt][0], bh[nt][1]);
                    mma16816(acc[mt][nt], al[mt], bh[nt][0], bh[nt][1]);
                }
#pragma unroll
            for (int np = 0; np < NT / 2; np++) {
                uint32_t rr[4];
                ldmBT(rr, bAddr[np] + BLOb + kB);
#pragma unroll
                for (int mt = 0; mt < 2; mt++) {
                    mma16816(acc[mt][2 * np],     ah[mt], rr[0], rr[1]);
                    mma16816(acc[mt][2 * np + 1], ah[mt], rr[2], rr[3]);
                }
            }
        }
        __syncthreads();
    }
}

#define EPI_ROW(mt, r)     (wm * 32 + (mt) * 16 + (lane >> 2) + (((r) >> 1) << 3))
#define EPI_COL(nt, r, NT) (wn * ((NT) * 8) + (nt) * 8 + ((lane & 3) << 1) + ((r) & 1))

// ============================================================================
// split kernels: fp32 -> (bf16 hi, bf16 lo). blockIdx.y selects tensor.
// ============================================================================
__global__ void split_act_kernel(const float* __restrict__ q,
                                 const float* __restrict__ k,
                                 const float* __restrict__ v)
{
    const float* x; bf16 *h, *l;
    switch (blockIdx.y) {
        case 0:  x = q; h = g_q_h; l = g_q_l; break;
        case 1:  x = k; h = g_k_h; l = g_k_l; break;
        default: x = v; h = g_v_h; l = g_v_l; break;
    }
    int i = blockIdx.x * blockDim.x + threadIdx.x;
    float val = x[i];
    bf16 hv = tobf(val);
    h[i] = hv;
    l[i] = tobf(val - __bfloat162float(hv));
}

__global__ void split_w_kernel(const float* __restrict__ Wq,
                               const float* __restrict__ Wk,
                               const float* __restrict__ Wv,
                               const float* __restrict__ Wo)
{
    const float* x; bf16 *h, *l;
    switch (blockIdx.y) {
        case 0:  x = Wq; h = g_Wq_h; l = g_Wq_l; break;
        case 1:  x = Wk; h = g_Wk_h; l = g_Wk_l; break;
        case 2:  x = Wv; h = g_Wv_h; l = g_Wv_l; break;
        default: x = Wo; h = g_Wo_h; l = g_Wo_l; break;
    }
    int i = blockIdx.x * blockDim.x + threadIdx.x;
    float val = x[i];
    bf16 hv = tobf(val);
    h[i] = hv;
    l[i] = tobf(val - __bfloat162float(hv));
}

// ============================================================================
// Merged projection GEMM: blockIdx.z = which (0=Q,1=K,2=V).
// ============================================================================
__global__ __launch_bounds__(256, 2) void proj_mma_kernel()
{
    const int which = blockIdx.z;
    const bf16 *Ah, *Wh;
    long loA, loW;
    if (which == 0)      { Ah = g_q_h; loA = g_q_l - g_q_h; Wh = g_Wq_h; loW = g_Wq_l - g_Wq_h; }
    else if (which == 1) { Ah = g_k_h; loA = g_k_l - g_k_h; Wh = g_Wk_h; loW = g_Wk_l - g_Wk_h; }
    else                 { Ah = g_v_h; loA = g_v_l - g_v_h; Wh = g_Wv_h; loW = g_Wv_l - g_Wv_h; }
    const float scale = (which == 0) ? 0.125f : 1.0f;

    const int bm = blockIdx.y * 128, bn = blockIdx.x * 128;
    float acc[2][8][4];
#pragma unroll
    for (int i = 0; i < 2; i++)
#pragma unroll
        for (int j = 0; j < 8; j++)
#pragma unroll
            for (int r = 0; r < 4; r++) acc[i][j][r] = 0.f;

    gemm_core<128>(Ah + bm * 1024, loA, 1024, Wh + bn, loW, 1024, 1024, acc);

    const int lane = threadIdx.x & 31, wid = threadIdx.x >> 5;
    const int wm = wid & 3, wn = wid >> 2;
    bf16 *dh, *dl;
    if (which == 0)      { dh = g_qp_h;  dl = g_qp_l;  }
    else if (which == 1) { dh = g_kpT_h; dl = g_kpT_l; }
    else                 { dh = g_vp_h;  dl = g_vp_l;  }

    if (which == 1) {
#pragma unroll
        for (int mt = 0; mt < 2; mt++)
#pragma unroll
            for (int nt = 0; nt < 8; nt++)
#pragma unroll
                for (int r = 0; r < 4; r++) {
                    int row = bm + EPI_ROW(mt, r);
                    int col = bn + EPI_COL(nt, r, 8);
                    int t = row >> 3, b = row & 7;
                    int h = col >> 6, d = col & 63;
                    int n = b * 16 + h;
                    float v = acc[mt][nt][r];
                    int idx = (n * 64 + d) * 512 + t;
                    bf16 hv = tobf(v);
                    dh[idx] = hv;
                    dl[idx] = tobf(v - __bfloat162float(hv));
                }
    } else {
#pragma unroll
        for (int mt = 0; mt < 2; mt++)
#pragma unroll
            for (int nt = 0; nt < 8; nt++)
#pragma unroll
                for (int r2 = 0; r2 < 4; r2 += 2) {
                    int row = bm + EPI_ROW(mt, r2);
                    int col = bn + EPI_COL(nt, r2, 8);   // even
                    int t = row >> 3, b = row & 7;
                    int h = col >> 6, d = col & 63;
                    int n = b * 16 + h;
                    int idx = (n * 512 + t) * 64 + d;
                    float v0 = acc[mt][nt][r2] * scale;
                    float v1 = acc[mt][nt][r2 + 1] * scale;
                    bf16 h0 = tobf(v0), h1 = tobf(v1);
                    __nv_bfloat162 hp; hp.x = h0; hp.y = h1;
                    __nv_bfloat162 lp;
                    lp.x = tobf(v0 - __bfloat162float(h0));
                    lp.y = tobf(v1 - __bfloat162float(h1));
                    *(__nv_bfloat162*)&dh[idx] = hp;
                    *(__nv_bfloat162*)&dl[idx] = lp;
                }
    }
}

// ============================================================================
// Energy + sigmoid -> g_p (fp32)
// ============================================================================
__global__ __launch_bounds__(256, 2) void energy_mma_kernel(const float* __restrict__ ebias)
{
    const int n = blockIdx.z;
    const int t0 = blockIdx.y * 128, s0 = blockIdx.x * 128;
    float acc[2][8][4];
#pragma unroll
    for (int i = 0; i < 2; i++)
#pragma unroll
        for (int j = 0; j < 8; j++)
#pragma unroll
            for (int r = 0; r < 4; r++) acc[i][j][r] = 0.f;

    gemm_core<128>(g_qp_h + n * 512 * 64 + t0 * 64, g_qp_l - g_qp_h, 64,
                   g_kpT_h + n * 64 * 512 + s0,     g_kpT_l - g_kpT_h, 512,
                   64, acc);

    const int lane = threadIdx.x & 31, wid = threadIdx.x >> 5;
    const int wm = wid & 3, wn = wid >> 2;
    const float eb = ebias[0];
#pragma unroll
    for (int mt = 0; mt < 2; mt++)
#pragma unroll
        for (int nt = 0; nt < 8; nt++)
#pragma unroll
            for (int r2 = 0; r2 < 4; r2 += 2) {
                int t = t0 + EPI_ROW(mt, r2);
                int s = s0 + EPI_COL(nt, r2, 8);
                float e0 = acc[mt][nt][r2] + eb;
                float e1 = acc[mt][nt][r2 + 1] + eb;
                float2 pv;
                pv.x = 1.f / (1.f + __expf(-e0));
                pv.y = 1.f / (1.f + __expf(-e1));
                *(float2*)&g_p[(n * 512 + t) * 512 + s] = pv;
            }
}

// ============================================================================
// Fused recurrence (R6 structure: 512 threads, interleaved scans, 3 barriers)
// + one-iteration-deep software prefetch of the g_p row:
// the row consumed by step t's "next-row cumprod" was loaded at step t-1,
// and step t issues the load for step t+1's row.
// One block per n (128 blocks), 512 threads (one per s).
// ============================================================================
__global__ __launch_bounds__(512) void recurrence_kernel()
{
    const int s = threadIdx.x;
    const int n = blockIdx.x;
    const int lane = s & 31, wid = s >> 5;
    const int base = n * 512 * 512 + s;

    __shared__ float sh_sw[16], sh_sp[16];
    __shared__ float sh_pw[16], sh_pp[16];
    __shared__ float sh_m[16];

    // ---- prologue: exclusive cumprod for t=0 ----
    float p = g_p[base];
    float pn_cur = g_p[base + 512];     // row 1, prefetched
    float cl, pc;
    {
        float v = 1.f - p;
#pragma unroll
        for (int o = 1; o < 32; o <<= 1) {
            float u = __shfl_up_sync(0xffffffffu, v, o);
            if (lane >= o) v *= u;
        }
        if (lane == 31) sh_pw[wid] = v;
        __syncthreads();
        if (wid == 0) {
            float w = (lane < 16) ? sh_pw[lane] : 1.f;
#pragma unroll
            for (int o = 1; o < 16; o <<= 1) {
                float u = __shfl_up_sync(0xffffffffu, w, o);
                if (lane >= o) w *= u;
            }
            if (lane < 16) sh_pp[lane] = w;
        }
        __syncthreads();
        float woff = (wid > 0) ? sh_pp[wid - 1] : 1.f;
        float inclp = v * woff;
        float cp = __shfl_up_sync(0xffffffffu, inclp, 1);
        if (lane == 0) cp = woff;
        if (s == 0) cp = 1.f;
        cl = fminf(fmaxf(cp, 1e-6f), 1.f);
        pc = p * cp;
    }
    float aprev = (s == 0) ? 1.f : 0.f;

    for (int t = 0; t < 512; t++) {
        // prefetch row t+2 (consumed next iteration) — full iteration to land
        float pn_nxt = (t < 510) ? g_p[base + (t + 2) * 512] : 0.f;
        float pnext = (t < 511) ? pn_cur : 0.f;

        // interleaved scans: sum of aprev/cl (row t), product of 1-pnext (t+1)
        float u2 = aprev / cl;
        float vb = 1.f - pnext;
#pragma unroll
        for (int o = 1; o < 32; o <<= 1) {
            float uu = __shfl_up_sync(0xffffffffu, u2, o);
            float vv = __shfl_up_sync(0xffffffffu, vb, o);
            if (lane >= o) { u2 += uu; vb *= vv; }
        }
        if (lane == 31) { sh_sw[wid] = u2; sh_pw[wid] = vb; }
        __syncthreads();
        if (wid == 0) {
            float w = (lane < 16) ? sh_sw[lane] : 0.f;
#pragma unroll
            for (int o = 1; o < 16; o <<= 1) {
                float uu = __shfl_up_sync(0xffffffffu, w, o);
                if (lane >= o) w += uu;
            }
            if (lane < 16) sh_sp[lane] = w;
        } else if (wid == 1) {
            float w = (lane < 16) ? sh_pw[lane] : 1.f;
#pragma unroll
            for (int o = 1; o < 16; o <<= 1) {
                float uu = __shfl_up_sync(0xffffffffu, w, o);
                if (lane >= o) w *= uu;
            }
            if (lane < 16) sh_pp[lane] = w;
        }
        __syncthreads();

        float incl2 = u2 + ((wid > 0) ? sh_sp[wid - 1] : 0.f);
        float araw = fminf(fmaxf(pc * incl2, 0.f), 1.f);

        // next-row cumprod finish
        float woff = (wid > 0) ? sh_pp[wid - 1] : 1.f;
        float inclp = vb * woff;
        float cpn = __shfl_up_sync(0xffffffffu, inclp, 1);
        if (lane == 0) cpn = woff;
        if (s == 0) cpn = 1.f;
        float cln = fminf(fmaxf(cpn, 1e-6f), 1.f);
        float pcn = pnext * cpn;

        if (s < 511) {
            bf16 hv = tobf(araw);
            g_al_h[base + t * 512] = hv;
            g_al_l[base + t * 512] = tobf(araw - __bfloat162float(hv));
        }

        float yv = (s < 511) ? araw : 0.f;
#pragma unroll
        for (int o = 16; o > 0; o >>= 1)
            yv += __shfl_xor_sync(0xffffffffu, yv, o);
        if (lane == 0) sh_m[wid] = yv;
        __syncthreads();

        if (s == 511) {
            float total = 0.f;
#pragma unroll
            for (int i = 0; i < 16; i++) total += sh_m[i];
            float aout = 1.f - fminf(fmaxf(total, 0.f), 1.f);
            bf16 hv = tobf(aout);
            g_al_h[base + t * 512] = hv;
            g_al_l[base + t * 512] = tobf(aout - __bfloat162float(hv));
        }

        aprev = araw;
        cl = cln;
        pc = pcn;
        pn_cur = pn_nxt;
    }
}

// ============================================================================
// attn = alpha @ vp  (per n: [512x512]@[512x64]) -> merged hi/lo.
// ============================================================================
__global__ __launch_bounds__(256, 2) void attnv_mma_kernel()
{
    const int n = blockIdx.z;
    const int t0 = blockIdx.y * 128;
    float acc[2][4][4];
#pragma unroll
    for (int i = 0; i < 2; i++)
#pragma unroll
        for (int j = 0; j < 4; j++)
#pragma unroll
            for (int r = 0; r < 4; r++) acc[i][j][r] = 0.f;

    gemm_core<64>(g_al_h + n * 512 * 512 + t0 * 512, g_al_l - g_al_h, 512,
                  g_vp_h + n * 512 * 64,             g_vp_l - g_vp_h, 64,
                  512, acc);

    const int lane = threadIdx.x & 31, wid = threadIdx.x >> 5;
    const int wm = wid & 3, wn = wid >> 2;
    const int b = n >> 4, h = n & 15;
#pragma unroll
    for (int mt = 0; mt < 2; mt++)
#pragma unroll
        for (int nt = 0; nt < 4; nt++)
#pragma unroll
            for (int r2 = 0; r2 < 4; r2 += 2) {
                int t = t0 + EPI_ROW(mt, r2);
                int d = EPI_COL(nt, r2, 4);
                int idx = (t * 8 + b) * 1024 + h * 64 + d;
                float v0 = acc[mt][nt][r2], v1 = acc[mt][nt][r2 + 1];
                bf16 h0 = tobf(v0), h1 = tobf(v1);
                __nv_bfloat162 hp; hp.x = h0; hp.y = h1;
                __nv_bfloat162 lp;
                lp.x = tobf(v0 - __bfloat162float(h0));
                lp.y = tobf(v1 - __bfloat162float(h1));
                *(__nv_bfloat162*)&g_at_h[idx] = hp;
                *(__nv_bfloat162*)&g_at_l[idx] = lp;
            }
}

// ============================================================================
// Output projection: out = attn[4096x1024] @ Wo + bo (fp32 out)
// ============================================================================
__global__ __launch_bounds__(256, 2) void out_mma_kernel(
    const float* __restrict__ bias, float* __restrict__ out)
{
    const int bm = blockIdx.y * 128, bn = blockIdx.x * 128;
    float acc[2][8][4];
#pragma unroll
    for (int i = 0; i < 2; i++)
#pragma unroll
        for (int j = 0; j < 8; j++)
#pragma unroll
            for (int r = 0; r < 4; r++) acc[i][j][r] = 0.f;

    gemm_core<128>(g_at_h + bm * 1024, g_at_l - g_at_h, 1024,
                   g_Wo_h + bn,        g_Wo_l - g_Wo_h, 1024, 1024, acc);

    const int lane = threadIdx.x & 31, wid = threadIdx.x >> 5;
    const int wm = wid & 3, wn = wid >> 2;
#pragma unroll
    for (int mt = 0; mt < 2; mt++)
#pragma unroll
        for (int nt = 0; nt < 8; nt++)
#pragma unroll
            for (int r2 = 0; r2 < 4; r2 += 2) {
                int row = bm + EPI_ROW(mt, r2);
                int col = bn + EPI_COL(nt, r2, 8);
                float2 ov;
                ov.x = acc[mt][nt][r2]     + bias[col];
                ov.y = acc[mt][nt][r2 + 1] + bias[col + 1];
                *(float2*)&out[row * 1024 + col] = ov;
            }
}

// ============================================================================
extern "C" void kernel_launch(void* const* d_in, const int* in_sizes, int n_in,
                              void* d_out, int out_size)
{
    const float* q  = (const float*)d_in[0];
    const float* k  = (const float*)d_in[1];
    const float* v  = (const float*)d_in[2];
    const float* Wq = (const float*)d_in[3];
    const float* Wk = (const float*)d_in[4];
    const float* Wv = (const float*)d_in[5];
    const float* Wo = (const float*)d_in[6];
    const float* bo = (const float*)d_in[7];
    const float* eb = (const float*)d_in[8];
    float* out = (float*)d_out;

    split_act_kernel<<<dim3(MROWS * EMBED / 256, 3), 256>>>(q, k, v);
    split_w_kernel<<<dim3(EMBED * EMBED / 256, 4), 256>>>(Wq, Wk, Wv, Wo);

    proj_mma_kernel<<<dim3(8, 32, 3), 256>>>();
    energy_mma_kernel<<<dim3(4, 4, 128), 256>>>(eb);
    recurrence_kernel<<<128, 512>>>();
    attnv_mma_kernel<<<dim3(1, 4, 128), 256>>>();
    out_mma_kernel<<<dim3(8, 32), 256>>>(bo, out);
}

// round 11
// speedup vs baseline: 1.1861x; 1.0449x over previous
#include <cuda_runtime.h>
#include <cuda_bf16.h>
#include <cstdint>

typedef __nv_bfloat16 bf16;

#define EMBED 1024
#define TT 512
#define SS 512
#define BATCH 8
#define NHB 128
#define MROWS 4096

// ---------------- scratch (static device globals; no allocation allowed) ----
__device__ bf16 g_q_h[MROWS*EMBED],  g_q_l[MROWS*EMBED];
__device__ bf16 g_k_h[MROWS*EMBED],  g_k_l[MROWS*EMBED];
__device__ bf16 g_v_h[MROWS*EMBED],  g_v_l[MROWS*EMBED];
__device__ bf16 g_Wq_h[EMBED*EMBED], g_Wq_l[EMBED*EMBED];
__device__ bf16 g_Wk_h[EMBED*EMBED], g_Wk_l[EMBED*EMBED];
__device__ bf16 g_Wv_h[EMBED*EMBED], g_Wv_l[EMBED*EMBED];
__device__ bf16 g_Wo_h[EMBED*EMBED], g_Wo_l[EMBED*EMBED];
__device__ bf16 g_qp_h [NHB*TT*64],  g_qp_l [NHB*TT*64];   // [n][t][d]
__device__ bf16 g_kpT_h[NHB*64*SS],  g_kpT_l[NHB*64*SS];   // [n][d][s]
__device__ bf16 g_vp_h [NHB*SS*64],  g_vp_l [NHB*SS*64];   // [n][s][d]
__device__ float g_p [NHB*TT*SS];                          // p_choose (fp32)
__device__ bf16 g_al_h[NHB*TT*SS],   g_al_l[NHB*TT*SS];    // alpha [n][t][s]
__device__ bf16 g_at_h[MROWS*EMBED], g_at_l[MROWS*EMBED];  // merged [t*8+b][h*64+d]

// ============================================================================
// PTX helpers
// ============================================================================
__device__ __forceinline__ uint32_t smem_u32(const void* p) {
    uint32_t a;
    asm("{ .reg .u64 t; cvta.to.shared.u64 t, %1; cvt.u32.u64 %0, t; }"
        : "=r"(a) : "l"(p));
    return a;
}
__device__ __forceinline__ void ldmA(uint32_t r[4], uint32_t addr) {
    asm volatile("ldmatrix.sync.aligned.m8n8.x4.shared.b16 {%0,%1,%2,%3},[%4];"
        : "=r"(r[0]), "=r"(r[1]), "=r"(r[2]), "=r"(r[3]) : "r"(addr));
}
__device__ __forceinline__ void ldmBT(uint32_t r[4], uint32_t addr) {
    asm volatile("ldmatrix.sync.aligned.m8n8.x4.trans.shared.b16 {%0,%1,%2,%3},[%4];"
        : "=r"(r[0]), "=r"(r[1]), "=r"(r[2]), "=r"(r[3]) : "r"(addr));
}
__device__ __forceinline__ void mma16816(float c[4], const uint32_t a[4],
                                         uint32_t b0, uint32_t b1) {
    asm volatile(
        "mma.sync.aligned.m16n8k16.row.col.f32.bf16.bf16.f32 "
        "{%0,%1,%2,%3},{%4,%5,%6,%7},{%8,%9},{%0,%1,%2,%3};"
        : "+f"(c[0]), "+f"(c[1]), "+f"(c[2]), "+f"(c[3])
        : "r"(a[0]), "r"(a[1]), "r"(a[2]), "r"(a[3]), "r"(b0), "r"(b1));
}
__device__ __forceinline__ void cp16(uint32_t dst, const void* src) {
    asm volatile("cp.async.ca.shared.global [%0], [%1], 16;"
        :: "r"(dst), "l"(src));
}
__device__ __forceinline__ void cp_commit() {
    asm volatile("cp.async.commit_group;");
}
template<int N>
__device__ __forceinline__ void cp_wait() {
    asm volatile("cp.async.wait_group %0;" :: "n"(N));
}
__device__ __forceinline__ bf16 tobf(float v) { return __float2bfloat16(v); }

// ============================================================================
// bf16x3 GEMM core (R6 config): 2-stage cp.async, static smem (2 CTA/SM),
// fragment reuse, precomputed shared addresses.
// acc += Ah*Bh + Ah*Bl + Al*Bh.   Al = Ah + loA elements, Bl = Bh + loB.
// Block = 128 x BN, 256 threads (8 warps, wm=wid&3, wn=wid>>2).
// ============================================================================
template<int BN>
__device__ __forceinline__ void gemm_core(
    const bf16* __restrict__ Ah, long loA, int lda,
    const bf16* __restrict__ Bh, long loB, int ldb,
    int K, float acc[2][BN/16][4])
{
    constexpr int NT = BN / 16;
    constexpr int BSTR = BN + 40;            // 20 banks mod 32 -> conflict-free
    constexpr int ASZ = 2 * 128 * 40;        // elements per stage (hi+lo)
    constexpr int BSZ = 2 * 32 * BSTR;
    constexpr uint32_t ALOb = 128 * 40 * 2;  // hi->lo byte offset within stage
    constexpr uint32_t BLOb = 32 * BSTR * 2;
    constexpr uint32_t ASTb = ASZ * 2;       // stage byte strides
    constexpr uint32_t BSTb = BSZ * 2;
    __shared__ bf16 sA[2 * ASZ];
    __shared__ bf16 sB[2 * BSZ];
    const int tid = threadIdx.x;
    const int lane = tid & 31, wid = tid >> 5;
    const int wm = wid & 3, wn = wid >> 2;
    const int nTiles = K / 32;
    const uint32_t sAu = smem_u32(sA), sBu = smem_u32(sB);

    const int aR = tid >> 2, aC = (tid & 3) * 8;
    const int aR2 = aR + 64;
    const bf16* srcA0 = Ah + aR * lda + aC;
    const bf16* srcA1 = Ah + aR2 * lda + aC;
    const uint32_t dA0 = sAu + (uint32_t)(aR * 40 + aC) * 2;
    const uint32_t dA1 = sAu + (uint32_t)(aR2 * 40 + aC) * 2;
    constexpr int BCH = (BN / 8) * 32 / 256;
    const bf16* srcB[BCH];
    uint32_t dB[BCH];
#pragma unroll
    for (int i = 0; i < BCH; i++) {
        int id = tid + i * 256;
        int rr = id / (BN / 8), cc = (id % (BN / 8)) * 8;
        srcB[i] = Bh + rr * ldb + cc;
        dB[i] = sBu + (uint32_t)(rr * BSTR + cc) * 2;
    }

    uint32_t bAddr[NT / 2];
#pragma unroll
    for (int np = 0; np < NT / 2; np++)
        bAddr[np] = sBu + (uint32_t)((lane & 15) * BSTR +
                     wn * (NT * 8) + np * 16 + ((lane >> 4) << 3)) * 2;
    uint32_t aAddr[2];
#pragma unroll
    for (int mt = 0; mt < 2; mt++)
        aAddr[mt] = sAu + (uint32_t)((wm * 32 + mt * 16 + (lane & 15)) * 40 +
                     ((lane >> 4) << 3)) * 2;

    auto loadTile = [&](uint32_t stA, uint32_t stB) {
        cp16(dA0 + stA, srcA0);  cp16(dA0 + ALOb + stA, srcA0 + loA);
        cp16(dA1 + stA, srcA1);  cp16(dA1 + ALOb + stA, srcA1 + loA);
        srcA0 += 32; srcA1 += 32;
#pragma unroll
        for (int i = 0; i < BCH; i++) {
            cp16(dB[i] + stB, srcB[i]);
            cp16(dB[i] + BLOb + stB, srcB[i] + loB);
            srcB[i] += 32 * ldb;
        }
    };

    loadTile(0, 0);
    cp_commit();

    for (int i = 0; i < nTiles; i++) {
        if (i + 1 < nTiles) {
            loadTile(((i + 1) & 1) ? ASTb : 0u, ((i + 1) & 1) ? BSTb : 0u);
            cp_commit();
            cp_wait<1>();
        } else {
            cp_wait<0>();
        }
        __syncthreads();

        const uint32_t stA = (i & 1) ? ASTb : 0u;
        const uint32_t stB = (i & 1) ? BSTb : 0u;
#pragma unroll
        for (int kk = 0; kk < 2; kk++) {
            const uint32_t kA = stA + (kk ? 32u : 0u);
            const uint32_t kB = stB + (kk ? 16u * BSTR * 2u : 0u);
            uint32_t bh[NT][2];
#pragma unroll
            for (int np = 0; np < NT / 2; np++) {
                uint32_t rr[4];
                ldmBT(rr, bAddr[np] + kB);
                bh[2 * np][0] = rr[0]; bh[2 * np][1] = rr[1];
                bh[2 * np + 1][0] = rr[2]; bh[2 * np + 1][1] = rr[3];
            }
            uint32_t ah[2][4], al[2][4];
#pragma unroll
            for (int mt = 0; mt < 2; mt++) {
                ldmA(ah[mt], aAddr[mt] + kA);
                ldmA(al[mt], aAddr[mt] + ALOb + kA);
            }
#pragma unroll
            for (int mt = 0; mt < 2; mt++)
#pragma unroll
                for (int nt = 0; nt < NT; nt++) {
                    mma16816(acc[mt][nt], ah[mt], bh[nt][0], bh[nt][1]);
                    mma16816(acc[mt][nt], al[mt], bh[nt][0], bh[nt][1]);
                }
#pragma unroll
            for (int np = 0; np < NT / 2; np++) {
                uint32_t rr[4];
                ldmBT(rr, bAddr[np] + BLOb + kB);
#pragma unroll
                for (int mt = 0; mt < 2; mt++) {
                    mma16816(acc[mt][2 * np],     ah[mt], rr[0], rr[1]);
                    mma16816(acc[mt][2 * np + 1], ah[mt], rr[2], rr[3]);
                }
            }
        }
        __syncthreads();
    }
}

#define EPI_ROW(mt, r)     (wm * 32 + (mt) * 16 + (lane >> 2) + (((r) >> 1) << 3))
#define EPI_COL(nt, r, NT) (wn * ((NT) * 8) + (nt) * 8 + ((lane & 3) << 1) + ((r) & 1))

// ============================================================================
// split kernels: fp32 -> (bf16 hi, bf16 lo), 4 elems/thread, vectorized.
// ============================================================================
__device__ __forceinline__ void split4(const float* __restrict__ x,
                                       bf16* __restrict__ h,
                                       bf16* __restrict__ l, int i)
{
    float4 v = *(const float4*)&x[i];
    bf16 h0 = tobf(v.x), h1 = tobf(v.y), h2 = tobf(v.z), h3 = tobf(v.w);
    __nv_bfloat162 H01, H23, L01, L23;
    H01.x = h0; H01.y = h1; H23.x = h2; H23.y = h3;
    L01.x = tobf(v.x - __bfloat162float(h0));
    L01.y = tobf(v.y - __bfloat162float(h1));
    L23.x = tobf(v.z - __bfloat162float(h2));
    L23.y = tobf(v.w - __bfloat162float(h3));
    uint2 H, L;
    H.x = *(uint32_t*)&H01; H.y = *(uint32_t*)&H23;
    L.x = *(uint32_t*)&L01; L.y = *(uint32_t*)&L23;
    *(uint2*)&h[i] = H;
    *(uint2*)&l[i] = L;
}

__global__ void split_act_kernel(const float* __restrict__ q,
                                 const float* __restrict__ k,
                                 const float* __restrict__ v)
{
    const float* x; bf16 *h, *l;
    switch (blockIdx.y) {
        case 0:  x = q; h = g_q_h; l = g_q_l; break;
        case 1:  x = k; h = g_k_h; l = g_k_l; break;
        default: x = v; h = g_v_h; l = g_v_l; break;
    }
    int i = (blockIdx.x * blockDim.x + threadIdx.x) * 4;
    split4(x, h, l, i);
}

__global__ void split_w_kernel(const float* __restrict__ Wq,
                               const float* __restrict__ Wk,
                               const float* __restrict__ Wv,
                               const float* __restrict__ Wo)
{
    const float* x; bf16 *h, *l;
    switch (blockIdx.y) {
        case 0:  x = Wq; h = g_Wq_h; l = g_Wq_l; break;
        case 1:  x = Wk; h = g_Wk_h; l = g_Wk_l; break;
        case 2:  x = Wv; h = g_Wv_h; l = g_Wv_l; break;
        default: x = Wo; h = g_Wo_h; l = g_Wo_l; break;
    }
    int i = (blockIdx.x * blockDim.x + threadIdx.x) * 4;
    split4(x, h, l, i);
}

// ============================================================================
// Projection GEMM: which = blockIdx.z + which_base (0=Q,1=K,2=V).
// ============================================================================
__global__ __launch_bounds__(256, 2) void proj_mma_kernel(int which_base)
{
    const int which = blockIdx.z + which_base;
    const bf16 *Ah, *Wh;
    long loA, loW;
    if (which == 0)      { Ah = g_q_h; loA = g_q_l - g_q_h; Wh = g_Wq_h; loW = g_Wq_l - g_Wq_h; }
    else if (which == 1) { Ah = g_k_h; loA = g_k_l - g_k_h; Wh = g_Wk_h; loW = g_Wk_l - g_Wk_h; }
    else                 { Ah = g_v_h; loA = g_v_l - g_v_h; Wh = g_Wv_h; loW = g_Wv_l - g_Wv_h; }
    const float scale = (which == 0) ? 0.125f : 1.0f;

    const int bm = blockIdx.y * 128, bn = blockIdx.x * 128;
    float acc[2][8][4];
#pragma unroll
    for (int i = 0; i < 2; i++)
#pragma unroll
        for (int j = 0; j < 8; j++)
#pragma unroll
            for (int r = 0; r < 4; r++) acc[i][j][r] = 0.f;

    gemm_core<128>(Ah + bm * 1024, loA, 1024, Wh + bn, loW, 1024, 1024, acc);

    const int lane = threadIdx.x & 31, wid = threadIdx.x >> 5;
    const int wm = wid & 3, wn = wid >> 2;
    bf16 *dh, *dl;
    if (which == 0)      { dh = g_qp_h;  dl = g_qp_l;  }
    else if (which == 1) { dh = g_kpT_h; dl = g_kpT_l; }
    else                 { dh = g_vp_h;  dl = g_vp_l;  }

    if (which == 1) {
#pragma unroll
        for (int mt = 0; mt < 2; mt++)
#pragma unroll
            for (int nt = 0; nt < 8; nt++)
#pragma unroll
                for (int r = 0; r < 4; r++) {
                    int row = bm + EPI_ROW(mt, r);
                    int col = bn + EPI_COL(nt, r, 8);
                    int t = row >> 3, b = row & 7;
                    int h = col >> 6, d = col & 63;
                    int n = b * 16 + h;
                    float v = acc[mt][nt][r];
                    int idx = (n * 64 + d) * 512 + t;
                    bf16 hv = tobf(v);
                    dh[idx] = hv;
                    dl[idx] = tobf(v - __bfloat162float(hv));
                }
    } else {
#pragma unroll
        for (int mt = 0; mt < 2; mt++)
#pragma unroll
            for (int nt = 0; nt < 8; nt++)
#pragma unroll
                for (int r2 = 0; r2 < 4; r2 += 2) {
                    int row = bm + EPI_ROW(mt, r2);
                    int col = bn + EPI_COL(nt, r2, 8);   // even
                    int t = row >> 3, b = row & 7;
                    int h = col >> 6, d = col & 63;
                    int n = b * 16 + h;
                    int idx = (n * 512 + t) * 64 + d;
                    float v0 = acc[mt][nt][r2] * scale;
                    float v1 = acc[mt][nt][r2 + 1] * scale;
                    bf16 h0 = tobf(v0), h1 = tobf(v1);
                    __nv_bfloat162 hp; hp.x = h0; hp.y = h1;
                    __nv_bfloat162 lp;
                    lp.x = tobf(v0 - __bfloat162float(h0));
                    lp.y = tobf(v1 - __bfloat162float(h1));
                    *(__nv_bfloat162*)&dh[idx] = hp;
                    *(__nv_bfloat162*)&dl[idx] = lp;
                }
    }
}

// ============================================================================
// Energy + sigmoid -> g_p (fp32)
// ============================================================================
__global__ __launch_bounds__(256, 2) void energy_mma_kernel(const float* __restrict__ ebias)
{
    const int n = blockIdx.z;
    const int t0 = blockIdx.y * 128, s0 = blockIdx.x * 128;
    float acc[2][8][4];
#pragma unroll
    for (int i = 0; i < 2; i++)
#pragma unroll
        for (int j = 0; j < 8; j++)
#pragma unroll
            for (int r = 0; r < 4; r++) acc[i][j][r] = 0.f;

    gemm_core<128>(g_qp_h + n * 512 * 64 + t0 * 64, g_qp_l - g_qp_h, 64,
                   g_kpT_h + n * 64 * 512 + s0,     g_kpT_l - g_kpT_h, 512,
                   64, acc);

    const int lane = threadIdx.x & 31, wid = threadIdx.x >> 5;
    const int wm = wid & 3, wn = wid >> 2;
    const float eb = ebias[0];
#pragma unroll
    for (int mt = 0; mt < 2; mt++)
#pragma unroll
        for (int nt = 0; nt < 8; nt++)
#pragma unroll
            for (int r2 = 0; r2 < 4; r2 += 2) {
                int t = t0 + EPI_ROW(mt, r2);
                int s = s0 + EPI_COL(nt, r2, 8);
                float e0 = acc[mt][nt][r2] + eb;
                float e1 = acc[mt][nt][r2 + 1] + eb;
                float2 pv;
                pv.x = 1.f / (1.f + __expf(-e0));
                pv.y = 1.f / (1.f + __expf(-e1));
                *(float2*)&g_p[(n * 512 + t) * 512 + s] = pv;
            }
}

// ============================================================================
// Fused recurrence — 512 threads, interleaved scans, TWO barriers per step.
// Mass-preservation fix of row t's last column is deferred to step t+1
// (double-buffered sh_m); row t is stored raw first, thread 511 corrects
// its own element one step later (same-thread program order).
// ============================================================================
__global__ __launch_bounds__(512) void recurrence_kernel()
{
    const int s = threadIdx.x;
    const int n = blockIdx.x;
    const int lane = s & 31, wid = s >> 5;
    const int base = n * 512 * 512 + s;

    __shared__ float sh_sw[16], sh_sp[16];
    __shared__ float sh_pw[16], sh_pp[16];
    __shared__ float sh_m[2][16];

    // ---- prologue: exclusive cumprod for t=0 ----
    float p = g_p[base];
    float pn_cur = g_p[base + 512];
    float cl, pc;
    {
        float v = 1.f - p;
#pragma unroll
        for (int o = 1; o < 32; o <<= 1) {
            float u = __shfl_up_sync(0xffffffffu, v, o);
            if (lane >= o) v *= u;
        }
        if (lane == 31) sh_pw[wid] = v;
        __syncthreads();
        if (wid == 0) {
            float w = (lane < 16) ? sh_pw[lane] : 1.f;
#pragma unroll
            for (int o = 1; o < 16; o <<= 1) {
                float u = __shfl_up_sync(0xffffffffu, w, o);
                if (lane >= o) w *= u;
            }
            if (lane < 16) sh_pp[lane] = w;
        }
        __syncthreads();
        float woff = (wid > 0) ? sh_pp[wid - 1] : 1.f;
        float inclp = v * woff;
        float cp = __shfl_up_sync(0xffffffffu, inclp, 1);
        if (lane == 0) cp = woff;
        if (s == 0) cp = 1.f;
        cl = fminf(fmaxf(cp, 1e-6f), 1.f);
        pc = p * cp;
    }
    float aprev = (s == 0) ? 1.f : 0.f;

    for (int t = 0; t < 512; t++) {
        const int buf = t & 1;
        float pn_nxt = (t < 510) ? g_p[base + (t + 2) * 512] : 0.f;
        float pnext = (t < 511) ? pn_cur : 0.f;

        // interleaved scans: sum of aprev/cl (row t), product of 1-pnext (t+1)
        float u2 = aprev / cl;
        float vb = 1.f - pnext;
#pragma unroll
        for (int o = 1; o < 32; o <<= 1) {
            float uu = __shfl_up_sync(0xffffffffu, u2, o);
            float vv = __shfl_up_sync(0xffffffffu, vb, o);
            if (lane >= o) { u2 += uu; vb *= vv; }
        }
        if (lane == 31) { sh_sw[wid] = u2; sh_pw[wid] = vb; }
        __syncthreads();                                   // barrier 1
        if (wid == 0) {
            float w = (lane < 16) ? sh_sw[lane] : 0.f;
#pragma unroll
            for (int o = 1; o < 16; o <<= 1) {
                float uu = __shfl_up_sync(0xffffffffu, w, o);
                if (lane >= o) w += uu;
            }
            if (lane < 16) sh_sp[lane] = w;
        } else if (wid == 1) {
            float w = (lane < 16) ? sh_pw[lane] : 1.f;
#pragma unroll
            for (int o = 1; o < 16; o <<= 1) {
                float uu = __shfl_up_sync(0xffffffffu, w, o);
                if (lane >= o) w *= uu;
            }
            if (lane < 16) sh_pp[lane] = w;
        }
        __syncthreads();                                   // barrier 2

        float incl2 = u2 + ((wid > 0) ? sh_sp[wid - 1] : 0.f);
        float araw = fminf(fmaxf(pc * incl2, 0.f), 1.f);

        // next-row cumprod finish
        float woff = (wid > 0) ? sh_pp[wid - 1] : 1.f;
        float inclp = vb * woff;
        float cpn = __shfl_up_sync(0xffffffffu, inclp, 1);
        if (lane == 0) cpn = woff;
        if (s == 0) cpn = 1.f;
        float cln = fminf(fmaxf(cpn, 1e-6f), 1.f);
        float pcn = pnext * cpn;

        // store row t raw (s=511 corrected next step by the same thread)
        {
            bf16 hv = tobf(araw);
            g_al_h[base + t * 512] = hv;
            g_al_l[base + t * 512] = tobf(araw - __bfloat162float(hv));
        }

        // mass reduction over clipped alpha (s < 511)
        float yv = (s < 511) ? araw : 0.f;
#pragma unroll
        for (int o = 16; o > 0; o >>= 1)
            yv += __shfl_xor_sync(0xffffffffu, yv, o);
        if (lane == 0) sh_m[buf][wid] = yv;

        // deferred: fix row t-1's last column (sh_m[1-buf] ordered by barrier1)
        if (t > 0 && s == 511) {
            float total = 0.f;
#pragma unroll
            for (int i = 0; i < 16; i++) total += sh_m[1 - buf][i];
            float aout = 1.f - fminf(fmaxf(total, 0.f), 1.f);
            bf16 hv = tobf(aout);
            g_al_h[base + (t - 1) * 512] = hv;
            g_al_l[base + (t - 1) * 512] = tobf(aout - __bfloat162float(hv));
        }

        aprev = araw;
        cl = cln;
        pc = pcn;
        pn_cur = pn_nxt;
    }

    // epilogue: row 511's last column (buf at t=511 is 1)
    __syncthreads();
    if (s == 511) {
        float total = 0.f;
#pragma unroll
        for (int i = 0; i < 16; i++) total += sh_m[1][i];
        float aout = 1.f - fminf(fmaxf(total, 0.f), 1.f);
        bf16 hv = tobf(aout);
        g_al_h[base + 511 * 512] = hv;
        g_al_l[base + 511 * 512] = tobf(aout - __bfloat162float(hv));
    }
}

// ============================================================================
// attn = alpha @ vp  (per n: [512x512]@[512x64]) -> merged hi/lo.
// ============================================================================
__global__ __launch_bounds__(256, 2) void attnv_mma_kernel()
{
    const int n = blockIdx.z;
    const int t0 = blockIdx.y * 128;
    float acc[2][4][4];
#pragma unroll
    for (int i = 0; i < 2; i++)
#pragma unroll
        for (int j = 0; j < 4; j++)
#pragma unroll
            for (int r = 0; r < 4; r++) acc[i][j][r] = 0.f;

    gemm_core<64>(g_al_h + n * 512 * 512 + t0 * 512, g_al_l - g_al_h, 512,
                  g_vp_h + n * 512 * 64,             g_vp_l - g_vp_h, 64,
                  512, acc);

    const int lane = threadIdx.x & 31, wid = threadIdx.x >> 5;
    const int wm = wid & 3, wn = wid >> 2;
    const int b = n >> 4, h = n & 15;
#pragma unroll
    for (int mt = 0; mt < 2; mt++)
#pragma unroll
        for (int nt = 0; nt < 4; nt++)
#pragma unroll
            for (int r2 = 0; r2 < 4; r2 += 2) {
                int t = t0 + EPI_ROW(mt, r2);
                int d = EPI_COL(nt, r2, 4);
                int idx = (t * 8 + b) * 1024 + h * 64 + d;
                float v0 = acc[mt][nt][r2], v1 = acc[mt][nt][r2 + 1];
                bf16 h0 = tobf(v0), h1 = tobf(v1);
                __nv_bfloat162 hp; hp.x = h0; hp.y = h1;
                __nv_bfloat162 lp;
                lp.x = tobf(v0 - __bfloat162float(h0));
                lp.y = tobf(v1 - __bfloat162float(h1));
                *(__nv_bfloat162*)&g_at_h[idx] = hp;
                *(__nv_bfloat162*)&g_at_l[idx] = lp;
            }
}

// ============================================================================
// Output projection: out = attn[4096x1024] @ Wo + bo (fp32 out)
// ============================================================================
__global__ __launch_bounds__(256, 2) void out_mma_kernel(
    const float* __restrict__ bias, float* __restrict__ out)
{
    const int bm = blockIdx.y * 128, bn = blockIdx.x * 128;
    float acc[2][8][4];
#pragma unroll
    for (int i = 0; i < 2; i++)
#pragma unroll
        for (int j = 0; j < 8; j++)
#pragma unroll
            for (int r = 0; r < 4; r++) acc[i][j][r] = 0.f;

    gemm_core<128>(g_at_h + bm * 1024, g_at_l - g_at_h, 1024,
                   g_Wo_h + bn,        g_Wo_l - g_Wo_h, 1024, 1024, acc);

    const int lane = threadIdx.x & 31, wid = threadIdx.x >> 5;
    const int wm = wid & 3, wn = wid >> 2;
#pragma unroll
    for (int mt = 0; mt < 2; mt++)
#pragma unroll
        for (int nt = 0; nt < 8; nt++)
#pragma unroll
            for (int r2 = 0; r2 < 4; r2 += 2) {
                int row = bm + EPI_ROW(mt, r2);
                int col = bn + EPI_COL(nt, r2, 8);
                float2 ov;
                ov.x = acc[mt][nt][r2]     + bias[col];
                ov.y = acc[mt][nt][r2 + 1] + bias[col + 1];
                *(float2*)&out[row * 1024 + col] = ov;
            }
}

// ============================================================================
extern "C" void kernel_launch(void* const* d_in, const int* in_sizes, int n_in,
                              void* d_out, int out_size)
{
    const float* q  = (const float*)d_in[0];
    const float* k  = (const float*)d_in[1];
    const float* v  = (const float*)d_in[2];
    const float* Wq = (const float*)d_in[3];
    const float* Wk = (const float*)d_in[4];
    const float* Wv = (const float*)d_in[5];
    const float* Wo = (const float*)d_in[6];
    const float* bo = (const float*)d_in[7];
    const float* eb = (const float*)d_in[8];
    float* out = (float*)d_out;

    // fork stream + events (created per call; a handful of calls total, so the
    // small host-side resource leak is bounded and no device memory is touched)
    cudaStream_t s2;
    cudaStreamCreateWithFlags(&s2, cudaStreamNonBlocking);
    cudaEvent_t e1, e2;
    cudaEventCreateWithFlags(&e1, cudaEventDisableTiming);
    cudaEventCreateWithFlags(&e2, cudaEventDisableTiming);

    split_act_kernel<<<dim3(MROWS * EMBED / 1024, 3), 256>>>(q, k, v);
    split_w_kernel<<<dim3(EMBED * EMBED / 1024, 4), 256>>>(Wq, Wk, Wv, Wo);

    cudaEventRecord(e1, 0);
    cudaStreamWaitEvent(s2, e1, 0);

    proj_mma_kernel<<<dim3(8, 32, 2), 256>>>(0);          // Q, K  (stream 0)
    proj_mma_kernel<<<dim3(8, 32, 1), 256, 0, s2>>>(2);   // V     (stream s2)
    cudaEventRecord(e2, s2);

    energy_mma_kernel<<<dim3(4, 4, 128), 256>>>(eb);
    recurrence_kernel<<<128, 512>>>();

    cudaStreamWaitEvent(0, e2, 0);                        // join V before attnv
    attnv_mma_kernel<<<dim3(1, 4, 128), 256>>>();
    out_mma_kernel<<<dim3(8, 32), 256>>>(bo, out);
}

// round 12
// speedup vs baseline: 1.3505x; 1.1385x over previous
#include <cuda_runtime.h>
#include <cuda_bf16.h>
#include <cstdint>

typedef __nv_bfloat16 bf16;

#define EMBED 1024
#define TT 512
#define SS 512
#define BATCH 8
#define NHB 128
#define MROWS 4096

// ---------------- scratch (static device globals; no allocation allowed) ----
__device__ bf16 g_q_h[MROWS*EMBED],  g_q_l[MROWS*EMBED];
__device__ bf16 g_k_h[MROWS*EMBED],  g_k_l[MROWS*EMBED];
__device__ bf16 g_v_h[MROWS*EMBED],  g_v_l[MROWS*EMBED];
__device__ bf16 g_Wq_h[EMBED*EMBED], g_Wq_l[EMBED*EMBED];
__device__ bf16 g_Wk_h[EMBED*EMBED], g_Wk_l[EMBED*EMBED];
__device__ bf16 g_Wv_h[EMBED*EMBED], g_Wv_l[EMBED*EMBED];
__device__ bf16 g_Wo_h[EMBED*EMBED], g_Wo_l[EMBED*EMBED];
__device__ bf16 g_qp_h [NHB*TT*64],  g_qp_l [NHB*TT*64];   // [n][t][d]
__device__ bf16 g_kpT_h[NHB*64*SS],  g_kpT_l[NHB*64*SS];   // [n][d][s]
__device__ bf16 g_vp_h [NHB*SS*64],  g_vp_l [NHB*SS*64];   // [n][s][d]
__device__ float g_p [NHB*TT*SS];                          // p_choose (fp32)
__device__ bf16 g_al_h[NHB*TT*SS],   g_al_l[NHB*TT*SS];    // alpha [n][t][s]
__device__ bf16 g_at_h[MROWS*EMBED], g_at_l[MROWS*EMBED];  // merged [t*8+b][h*64+d]

// ============================================================================
// PTX helpers
// ============================================================================
__device__ __forceinline__ uint32_t smem_u32(const void* p) {
    uint32_t a;
    asm("{ .reg .u64 t; cvta.to.shared.u64 t, %1; cvt.u32.u64 %0, t; }"
        : "=r"(a) : "l"(p));
    return a;
}
__device__ __forceinline__ void ldmA(uint32_t r[4], uint32_t addr) {
    asm volatile("ldmatrix.sync.aligned.m8n8.x4.shared.b16 {%0,%1,%2,%3},[%4];"
        : "=r"(r[0]), "=r"(r[1]), "=r"(r[2]), "=r"(r[3]) : "r"(addr));
}
__device__ __forceinline__ void ldmBT(uint32_t r[4], uint32_t addr) {
    asm volatile("ldmatrix.sync.aligned.m8n8.x4.trans.shared.b16 {%0,%1,%2,%3},[%4];"
        : "=r"(r[0]), "=r"(r[1]), "=r"(r[2]), "=r"(r[3]) : "r"(addr));
}
__device__ __forceinline__ void mma16816(float c[4], const uint32_t a[4],
                                         uint32_t b0, uint32_t b1) {
    asm volatile(
        "mma.sync.aligned.m16n8k16.row.col.f32.bf16.bf16.f32 "
        "{%0,%1,%2,%3},{%4,%5,%6,%7},{%8,%9},{%0,%1,%2,%3};"
        : "+f"(c[0]), "+f"(c[1]), "+f"(c[2]), "+f"(c[3])
        : "r"(a[0]), "r"(a[1]), "r"(a[2]), "r"(a[3]), "r"(b0), "r"(b1));
}
__device__ __forceinline__ void cp16(uint32_t dst, const void* src) {
    asm volatile("cp.async.ca.shared.global [%0], [%1], 16;"
        :: "r"(dst), "l"(src));
}
__device__ __forceinline__ void cp_commit() {
    asm volatile("cp.async.commit_group;");
}
template<int N>
__device__ __forceinline__ void cp_wait() {
    asm volatile("cp.async.wait_group %0;" :: "n"(N));
}
__device__ __forceinline__ bf16 tobf(float v) { return __float2bfloat16(v); }

// ============================================================================
// bf16x3 GEMM core (R6 config): 2-stage cp.async, static smem (2 CTA/SM),
// fragment reuse, precomputed shared addresses.
// acc += Ah*Bh + Ah*Bl + Al*Bh.   Al = Ah + loA elements, Bl = Bh + loB.
// Block = 128 x BN, 256 threads (8 warps, wm=wid&3, wn=wid>>2).
// ============================================================================
template<int BN>
__device__ __forceinline__ void gemm_core(
    const bf16* __restrict__ Ah, long loA, int lda,
    const bf16* __restrict__ Bh, long loB, int ldb,
    int K, float acc[2][BN/16][4])
{
    constexpr int NT = BN / 16;
    constexpr int BSTR = BN + 40;            // 20 banks mod 32 -> conflict-free
    constexpr int ASZ = 2 * 128 * 40;        // elements per stage (hi+lo)
    constexpr int BSZ = 2 * 32 * BSTR;
    constexpr uint32_t ALOb = 128 * 40 * 2;  // hi->lo byte offset within stage
    constexpr uint32_t BLOb = 32 * BSTR * 2;
    constexpr uint32_t ASTb = ASZ * 2;       // stage byte strides
    constexpr uint32_t BSTb = BSZ * 2;
    __shared__ bf16 sA[2 * ASZ];
    __shared__ bf16 sB[2 * BSZ];
    const int tid = threadIdx.x;
    const int lane = tid & 31, wid = tid >> 5;
    const int wm = wid & 3, wn = wid >> 2;
    const int nTiles = K / 32;
    const uint32_t sAu = smem_u32(sA), sBu = smem_u32(sB);

    const int aR = tid >> 2, aC = (tid & 3) * 8;
    const int aR2 = aR + 64;
    const bf16* srcA0 = Ah + aR * lda + aC;
    const bf16* srcA1 = Ah + aR2 * lda + aC;
    const uint32_t dA0 = sAu + (uint32_t)(aR * 40 + aC) * 2;
    const uint32_t dA1 = sAu + (uint32_t)(aR2 * 40 + aC) * 2;
    constexpr int BCH = (BN / 8) * 32 / 256;
    const bf16* srcB[BCH];
    uint32_t dB[BCH];
#pragma unroll
    for (int i = 0; i < BCH; i++) {
        int id = tid + i * 256;
        int rr = id / (BN / 8), cc = (id % (BN / 8)) * 8;
        srcB[i] = Bh + rr * ldb + cc;
        dB[i] = sBu + (uint32_t)(rr * BSTR + cc) * 2;
    }

    uint32_t bAddr[NT / 2];
#pragma unroll
    for (int np = 0; np < NT / 2; np++)
        bAddr[np] = sBu + (uint32_t)((lane & 15) * BSTR +
                     wn * (NT * 8) + np * 16 + ((lane >> 4) << 3)) * 2;
    uint32_t aAddr[2];
#pragma unroll
    for (int mt = 0; mt < 2; mt++)
        aAddr[mt] = sAu + (uint32_t)((wm * 32 + mt * 16 + (lane & 15)) * 40 +
                     ((lane >> 4) << 3)) * 2;

    auto loadTile = [&](uint32_t stA, uint32_t stB) {
        cp16(dA0 + stA, srcA0);  cp16(dA0 + ALOb + stA, srcA0 + loA);
        cp16(dA1 + stA, srcA1);  cp16(dA1 + ALOb + stA, srcA1 + loA);
        srcA0 += 32; srcA1 += 32;
#pragma unroll
        for (int i = 0; i < BCH; i++) {
            cp16(dB[i] + stB, srcB[i]);
            cp16(dB[i] + BLOb + stB, srcB[i] + loB);
            srcB[i] += 32 * ldb;
        }
    };

    loadTile(0, 0);
    cp_commit();

    for (int i = 0; i < nTiles; i++) {
        if (i + 1 < nTiles) {
            loadTile(((i + 1) & 1) ? ASTb : 0u, ((i + 1) & 1) ? BSTb : 0u);
            cp_commit();
            cp_wait<1>();
        } else {
            cp_wait<0>();
        }
        __syncthreads();

        const uint32_t stA = (i & 1) ? ASTb : 0u;
        const uint32_t stB = (i & 1) ? BSTb : 0u;
#pragma unroll
        for (int kk = 0; kk < 2; kk++) {
            const uint32_t kA = stA + (kk ? 32u : 0u);
            const uint32_t kB = stB + (kk ? 16u * BSTR * 2u : 0u);
            uint32_t bh[NT][2];
#pragma unroll
            for (int np = 0; np < NT / 2; np++) {
                uint32_t rr[4];
                ldmBT(rr, bAddr[np] + kB);
                bh[2 * np][0] = rr[0]; bh[2 * np][1] = rr[1];
                bh[2 * np + 1][0] = rr[2]; bh[2 * np + 1][1] = rr[3];
            }
            uint32_t ah[2][4], al[2][4];
#pragma unroll
            for (int mt = 0; mt < 2; mt++) {
                ldmA(ah[mt], aAddr[mt] + kA);
                ldmA(al[mt], aAddr[mt] + ALOb + kA);
            }
#pragma unroll
            for (int mt = 0; mt < 2; mt++)
#pragma unroll
                for (int nt = 0; nt < NT; nt++) {
                    mma16816(acc[mt][nt], ah[mt], bh[nt][0], bh[nt][1]);
                    mma16816(acc[mt][nt], al[mt], bh[nt][0], bh[nt][1]);
                }
#pragma unroll
            for (int np = 0; np < NT / 2; np++) {
                uint32_t rr[4];
                ldmBT(rr, bAddr[np] + BLOb + kB);
#pragma unroll
                for (int mt = 0; mt < 2; mt++) {
                    mma16816(acc[mt][2 * np],     ah[mt], rr[0], rr[1]);
                    mma16816(acc[mt][2 * np + 1], ah[mt], rr[2], rr[3]);
                }
            }
        }
        __syncthreads();
    }
}

#define EPI_ROW(mt, r)     (wm * 32 + (mt) * 16 + (lane >> 2) + (((r) >> 1) << 3))
#define EPI_COL(nt, r, NT) (wn * ((NT) * 8) + (nt) * 8 + ((lane & 3) << 1) + ((r) & 1))

// ============================================================================
// split kernels: fp32 -> (bf16 hi, bf16 lo), 4 elems/thread, vectorized.
// ============================================================================
__device__ __forceinline__ void split4(const float* __restrict__ x,
                                       bf16* __restrict__ h,
                                       bf16* __restrict__ l, int i)
{
    float4 v = *(const float4*)&x[i];
    bf16 h0 = tobf(v.x), h1 = tobf(v.y), h2 = tobf(v.z), h3 = tobf(v.w);
    __nv_bfloat162 H01, H23, L01, L23;
    H01.x = h0; H01.y = h1; H23.x = h2; H23.y = h3;
    L01.x = tobf(v.x - __bfloat162float(h0));
    L01.y = tobf(v.y - __bfloat162float(h1));
    L23.x = tobf(v.z - __bfloat162float(h2));
    L23.y = tobf(v.w - __bfloat162float(h3));
    uint2 H, L;
    H.x = *(uint32_t*)&H01; H.y = *(uint32_t*)&H23;
    L.x = *(uint32_t*)&L01; L.y = *(uint32_t*)&L23;
    *(uint2*)&h[i] = H;
    *(uint2*)&l[i] = L;
}

__global__ void split_act_kernel(const float* __restrict__ q,
                                 const float* __restrict__ k,
                                 const float* __restrict__ v)
{
    const float* x; bf16 *h, *l;
    switch (blockIdx.y) {
        case 0:  x = q; h = g_q_h; l = g_q_l; break;
        case 1:  x = k; h = g_k_h; l = g_k_l; break;
        default: x = v; h = g_v_h; l = g_v_l; break;
    }
    int i = (blockIdx.x * blockDim.x + threadIdx.x) * 4;
    split4(x, h, l, i);
}

__global__ void split_w_kernel(const float* __restrict__ Wq,
                               const float* __restrict__ Wk,
                               const float* __restrict__ Wv,
                               const float* __restrict__ Wo)
{
    const float* x; bf16 *h, *l;
    switch (blockIdx.y) {
        case 0:  x = Wq; h = g_Wq_h; l = g_Wq_l; break;
        case 1:  x = Wk; h = g_Wk_h; l = g_Wk_l; break;
        case 2:  x = Wv; h = g_Wv_h; l = g_Wv_l; break;
        default: x = Wo; h = g_Wo_h; l = g_Wo_l; break;
    }
    int i = (blockIdx.x * blockDim.x + threadIdx.x) * 4;
    split4(x, h, l, i);
}

// ============================================================================
// Projection GEMM: which = blockIdx.z + which_base (0=Q,1=K,2=V).
// ============================================================================
__global__ __launch_bounds__(256, 2) void proj_mma_kernel(int which_base)
{
    const int which = blockIdx.z + which_base;
    const bf16 *Ah, *Wh;
    long loA, loW;
    if (which == 0)      { Ah = g_q_h; loA = g_q_l - g_q_h; Wh = g_Wq_h; loW = g_Wq_l - g_Wq_h; }
    else if (which == 1) { Ah = g_k_h; loA = g_k_l - g_k_h; Wh = g_Wk_h; loW = g_Wk_l - g_Wk_h; }
    else                 { Ah = g_v_h; loA = g_v_l - g_v_h; Wh = g_Wv_h; loW = g_Wv_l - g_Wv_h; }
    const float scale = (which == 0) ? 0.125f : 1.0f;

    const int bm = blockIdx.y * 128, bn = blockIdx.x * 128;
    float acc[2][8][4];
#pragma unroll
    for (int i = 0; i < 2; i++)
#pragma unroll
        for (int j = 0; j < 8; j++)
#pragma unroll
            for (int r = 0; r < 4; r++) acc[i][j][r] = 0.f;

    gemm_core<128>(Ah + bm * 1024, loA, 1024, Wh + bn, loW, 1024, 1024, acc);

    const int lane = threadIdx.x & 31, wid = threadIdx.x >> 5;
    const int wm = wid & 3, wn = wid >> 2;
    bf16 *dh, *dl;
    if (which == 0)      { dh = g_qp_h;  dl = g_qp_l;  }
    else if (which == 1) { dh = g_kpT_h; dl = g_kpT_l; }
    else                 { dh = g_vp_h;  dl = g_vp_l;  }

    if (which == 1) {
#pragma unroll
        for (int mt = 0; mt < 2; mt++)
#pragma unroll
            for (int nt = 0; nt < 8; nt++)
#pragma unroll
                for (int r = 0; r < 4; r++) {
                    int row = bm + EPI_ROW(mt, r);
                    int col = bn + EPI_COL(nt, r, 8);
                    int t = row >> 3, b = row & 7;
                    int h = col >> 6, d = col & 63;
                    int n = b * 16 + h;
                    float v = acc[mt][nt][r];
                    int idx = (n * 64 + d) * 512 + t;
                    bf16 hv = tobf(v);
                    dh[idx] = hv;
                    dl[idx] = tobf(v - __bfloat162float(hv));
                }
    } else {
#pragma unroll
        for (int mt = 0; mt < 2; mt++)
#pragma unroll
            for (int nt = 0; nt < 8; nt++)
#pragma unroll
                for (int r2 = 0; r2 < 4; r2 += 2) {
                    int row = bm + EPI_ROW(mt, r2);
                    int col = bn + EPI_COL(nt, r2, 8);   // even
                    int t = row >> 3, b = row & 7;
                    int h = col >> 6, d = col & 63;
                    int n = b * 16 + h;
                    int idx = (n * 512 + t) * 64 + d;
                    float v0 = acc[mt][nt][r2] * scale;
                    float v1 = acc[mt][nt][r2 + 1] * scale;
                    bf16 h0 = tobf(v0), h1 = tobf(v1);
                    __nv_bfloat162 hp; hp.x = h0; hp.y = h1;
                    __nv_bfloat162 lp;
                    lp.x = tobf(v0 - __bfloat162float(h0));
                    lp.y = tobf(v1 - __bfloat162float(h1));
                    *(__nv_bfloat162*)&dh[idx] = hp;
                    *(__nv_bfloat162*)&dl[idx] = lp;
                }
    }
}

// ============================================================================
// Energy + sigmoid -> g_p (fp32)
// ============================================================================
__global__ __launch_bounds__(256, 2) void energy_mma_kernel(const float* __restrict__ ebias)
{
    const int n = blockIdx.z;
    const int t0 = blockIdx.y * 128, s0 = blockIdx.x * 128;
    float acc[2][8][4];
#pragma unroll
    for (int i = 0; i < 2; i++)
#pragma unroll
        for (int j = 0; j < 8; j++)
#pragma unroll
            for (int r = 0; r < 4; r++) acc[i][j][r] = 0.f;

    gemm_core<128>(g_qp_h + n * 512 * 64 + t0 * 64, g_qp_l - g_qp_h, 64,
                   g_kpT_h + n * 64 * 512 + s0,     g_kpT_l - g_kpT_h, 512,
                   64, acc);

    const int lane = threadIdx.x & 31, wid = threadIdx.x >> 5;
    const int wm = wid & 3, wn = wid >> 2;
    const float eb = ebias[0];
#pragma unroll
    for (int mt = 0; mt < 2; mt++)
#pragma unroll
        for (int nt = 0; nt < 8; nt++)
#pragma unroll
            for (int r2 = 0; r2 < 4; r2 += 2) {
                int t = t0 + EPI_ROW(mt, r2);
                int s = s0 + EPI_COL(nt, r2, 8);
                float e0 = acc[mt][nt][r2] + eb;
                float e1 = acc[mt][nt][r2 + 1] + eb;
                float2 pv;
                pv.x = 1.f / (1.f + __expf(-e0));
                pv.y = 1.f / (1.f + __expf(-e1));
                *(float2*)&g_p[(n * 512 + t) * 512 + s] = pv;
            }
}

// ============================================================================
// Fused recurrence — ONE WARP per head, 16 s-elements per lane, NO barriers.
// All cross-element combining = register-serial prefixes + one 5-shfl warp
// scan (sum & product chains interleaved).  Lane 31 owns s=511: mass fix is
// computed inline from the shfl-reduced total and stored directly, while the
// RAW clipped alpha carries to step t+1 (matches reference scan semantics).
// grid = 128 (one block = one warp = one head).
// ============================================================================
__global__ __launch_bounds__(32) void recurrence_kernel()
{
    const int lane = threadIdx.x;
    const int n = blockIdx.x;
    const long base = (long)n * (512 * 512) + lane * 16;

    float ap[16], cl[16], pc[16];

    // ---- prologue: exclusive cumprod of (1-p) for row 0 ----
    {
        float pr[16];
#pragma unroll
        for (int q4 = 0; q4 < 4; q4++) {
            float4 v = *(const float4*)&g_p[base + q4 * 4];
            pr[q4 * 4 + 0] = v.x; pr[q4 * 4 + 1] = v.y;
            pr[q4 * 4 + 2] = v.z; pr[q4 * 4 + 3] = v.w;
        }
        float lp[16];
        lp[0] = 1.f - pr[0];
#pragma unroll
        for (int j = 1; j < 16; j++) lp[j] = lp[j - 1] * (1.f - pr[j]);
        float V = lp[15];
#pragma unroll
        for (int o = 1; o < 32; o <<= 1) {
            float vv = __shfl_up_sync(0xffffffffu, V, o);
            if (lane >= o) V *= vv;
        }
        float Vex = __shfl_up_sync(0xffffffffu, V, 1);
        if (lane == 0) Vex = 1.f;
        float ex = Vex;
#pragma unroll
        for (int j = 0; j < 16; j++) {
            cl[j] = fminf(fmaxf(ex, 1e-6f), 1.f);
            pc[j] = pr[j] * ex;
            ex = Vex * lp[j];          // exclusive prefix for element j+1
        }
    }
#pragma unroll
    for (int j = 0; j < 16; j++) ap[j] = 0.f;
    if (lane == 0) ap[0] = 1.f;

    for (int t = 0; t < 512; t++) {
        // load next row early (consumed only in the second half of the step)
        float pn[16];
        if (t < 511) {
#pragma unroll
            for (int q4 = 0; q4 < 4; q4++) {
                float4 v = *(const float4*)&g_p[base + (long)(t + 1) * 512 + q4 * 4];
                pn[q4 * 4 + 0] = v.x; pn[q4 * 4 + 1] = v.y;
                pn[q4 * 4 + 2] = v.z; pn[q4 * 4 + 3] = v.w;
            }
        } else {
#pragma unroll
            for (int j = 0; j < 16; j++) pn[j] = 0.f;
        }

        // ---- local inclusive prefix sum of aprev/cl ----
        float ls[16];
        ls[0] = __fdividef(ap[0], cl[0]);
#pragma unroll
        for (int j = 1; j < 16; j++)
            ls[j] = ls[j - 1] + __fdividef(ap[j], cl[j]);

        // ---- local inclusive prefix product of (1 - pnext) ----
        float lp[16];
        lp[0] = 1.f - pn[0];
#pragma unroll
        for (int j = 1; j < 16; j++) lp[j] = lp[j - 1] * (1.f - pn[j]);

        // ---- interleaved warp scans over lane totals ----
        float U = ls[15], V = lp[15];
#pragma unroll
        for (int o = 1; o < 32; o <<= 1) {
            float uu = __shfl_up_sync(0xffffffffu, U, o);
            float vv = __shfl_up_sync(0xffffffffu, V, o);
            if (lane >= o) { U += uu; V *= vv; }
        }
        float Uex = __shfl_up_sync(0xffffffffu, U, 1);
        float Vex = __shfl_up_sync(0xffffffffu, V, 1);
        if (lane == 0) { Uex = 0.f; Vex = 1.f; }

        // ---- alpha row t ----
        float araw[16];
#pragma unroll
        for (int j = 0; j < 16; j++)
            araw[j] = fminf(fmaxf(pc[j] * (Uex + ls[j]), 0.f), 1.f);

        // ---- mass total over s < 511 (shfl reduce; no barrier) ----
        float m = 0.f;
#pragma unroll
        for (int j = 0; j < 16; j++) m += araw[j];
        if (lane == 31) m -= araw[15];
#pragma unroll
        for (int o = 16; o > 0; o >>= 1)
            m += __shfl_xor_sync(0xffffffffu, m, o);

        // ---- next-row exclusive cumprod -> cl/pc for step t+1 ----
        {
            float ex = Vex;
#pragma unroll
            for (int j = 0; j < 16; j++) {
                cl[j] = fminf(fmaxf(ex, 1e-6f), 1.f);
                pc[j] = pn[j] * ex;
                ex = Vex * lp[j];
            }
        }

        // ---- store row t (lane 31 writes mass-fixed last column) ----
        {
            float v15 = araw[15];
            if (lane == 31) v15 = 1.f - fminf(fmaxf(m, 0.f), 1.f);
            uint4 H, L;
            uint32_t hw[8], lw[8];
#pragma unroll
            for (int j2 = 0; j2 < 8; j2++) {
                float v0 = (j2 * 2 == 15) ? v15 : araw[j2 * 2];
                float v1 = (j2 * 2 + 1 == 15) ? v15 : araw[j2 * 2 + 1];
                __nv_bfloat162 hp, lpp;
                hp.x = tobf(v0); hp.y = tobf(v1);
                lpp.x = tobf(v0 - __bfloat162float(hp.x));
                lpp.y = tobf(v1 - __bfloat162float(hp.y));
                hw[j2] = *(uint32_t*)&hp;
                lw[j2] = *(uint32_t*)&lpp;
            }
            H.x = hw[0]; H.y = hw[1]; H.z = hw[2]; H.w = hw[3];
            L.x = lw[0]; L.y = lw[1]; L.z = lw[2]; L.w = lw[3];
            *(uint4*)&g_al_h[base + (long)t * 512] = H;
            *(uint4*)&g_al_l[base + (long)t * 512] = L;
            H.x = hw[4]; H.y = hw[5]; H.z = hw[6]; H.w = hw[7];
            L.x = lw[4]; L.y = lw[5]; L.z = lw[6]; L.w = lw[7];
            *(uint4*)&g_al_h[base + (long)t * 512 + 8] = H;
            *(uint4*)&g_al_l[base + (long)t * 512 + 8] = L;
        }

        // carry RAW clipped alpha
#pragma unroll
        for (int j = 0; j < 16; j++) ap[j] = araw[j];
    }
}

// ============================================================================
// attn = alpha @ vp  (per n: [512x512]@[512x64]) -> merged hi/lo.
// ============================================================================
__global__ __launch_bounds__(256, 2) void attnv_mma_kernel()
{
    const int n = blockIdx.z;
    const int t0 = blockIdx.y * 128;
    float acc[2][4][4];
#pragma unroll
    for (int i = 0; i < 2; i++)
#pragma unroll
        for (int j = 0; j < 4; j++)
#pragma unroll
            for (int r = 0; r < 4; r++) acc[i][j][r] = 0.f;

    gemm_core<64>(g_al_h + n * 512 * 512 + t0 * 512, g_al_l - g_al_h, 512,
                  g_vp_h + n * 512 * 64,             g_vp_l - g_vp_h, 64,
                  512, acc);

    const int lane = threadIdx.x & 31, wid = threadIdx.x >> 5;
    const int wm = wid & 3, wn = wid >> 2;
    const int b = n >> 4, h = n & 15;
#pragma unroll
    for (int mt = 0; mt < 2; mt++)
#pragma unroll
        for (int nt = 0; nt < 4; nt++)
#pragma unroll
            for (int r2 = 0; r2 < 4; r2 += 2) {
                int t = t0 + EPI_ROW(mt, r2);
                int d = EPI_COL(nt, r2, 4);
                int idx = (t * 8 + b) * 1024 + h * 64 + d;
                float v0 = acc[mt][nt][r2], v1 = acc[mt][nt][r2 + 1];
                bf16 h0 = tobf(v0), h1 = tobf(v1);
                __nv_bfloat162 hp; hp.x = h0; hp.y = h1;
                __nv_bfloat162 lp;
                lp.x = tobf(v0 - __bfloat162float(h0));
                lp.y = tobf(v1 - __bfloat162float(h1));
                *(__nv_bfloat162*)&g_at_h[idx] = hp;
                *(__nv_bfloat162*)&g_at_l[idx] = lp;
            }
}

// ============================================================================
// Output projection: out = attn[4096x1024] @ Wo + bo (fp32 out)
// ============================================================================
__global__ __launch_bounds__(256, 2) void out_mma_kernel(
    const float* __restrict__ bias, float* __restrict__ out)
{
    const int bm = blockIdx.y * 128, bn = blockIdx.x * 128;
    float acc[2][8][4];
#pragma unroll
    for (int i = 0; i < 2; i++)
#pragma unroll
        for (int j = 0; j < 8; j++)
#pragma unroll
            for (int r = 0; r < 4; r++) acc[i][j][r] = 0.f;

    gemm_core<128>(g_at_h + bm * 1024, g_at_l - g_at_h, 1024,
                   g_Wo_h + bn,        g_Wo_l - g_Wo_h, 1024, 1024, acc);

    const int lane = threadIdx.x & 31, wid = threadIdx.x >> 5;
    const int wm = wid & 3, wn = wid >> 2;
#pragma unroll
    for (int mt = 0; mt < 2; mt++)
#pragma unroll
        for (int nt = 0; nt < 8; nt++)
#pragma unroll
            for (int r2 = 0; r2 < 4; r2 += 2) {
                int row = bm + EPI_ROW(mt, r2);
                int col = bn + EPI_COL(nt, r2, 8);
                float2 ov;
                ov.x = acc[mt][nt][r2]     + bias[col];
                ov.y = acc[mt][nt][r2 + 1] + bias[col + 1];
                *(float2*)&out[row * 1024 + col] = ov;
            }
}

// ============================================================================
extern "C" void kernel_launch(void* const* d_in, const int* in_sizes, int n_in,
                              void* d_out, int out_size)
{
    const float* q  = (const float*)d_in[0];
    const float* k  = (const float*)d_in[1];
    const float* v  = (const float*)d_in[2];
    const float* Wq = (const float*)d_in[3];
    const float* Wk = (const float*)d_in[4];
    const float* Wv = (const float*)d_in[5];
    const float* Wo = (const float*)d_in[6];
    const float* bo = (const float*)d_in[7];
    const float* eb = (const float*)d_in[8];
    float* out = (float*)d_out;

    cudaStream_t s2;
    cudaStreamCreateWithFlags(&s2, cudaStreamNonBlocking);
    cudaEvent_t e1, e2;
    cudaEventCreateWithFlags(&e1, cudaEventDisableTiming);
    cudaEventCreateWithFlags(&e2, cudaEventDisableTiming);

    split_act_kernel<<<dim3(MROWS * EMBED / 1024, 3), 256>>>(q, k, v);
    split_w_kernel<<<dim3(EMBED * EMBED / 1024, 4), 256>>>(Wq, Wk, Wv, Wo);

    cudaEventRecord(e1, 0);
    cudaStreamWaitEvent(s2, e1, 0);

    proj_mma_kernel<<<dim3(8, 32, 2), 256>>>(0);          // Q, K  (stream 0)
    proj_mma_kernel<<<dim3(8, 32, 1), 256, 0, s2>>>(2);   // V     (stream s2)
    cudaEventRecord(e2, s2);

    energy_mma_kernel<<<dim3(4, 4, 128), 256>>>(eb);
    recurrence_kernel<<<128, 32>>>();

    cudaStreamWaitEvent(0, e2, 0);                        // join V before attnv
    attnv_mma_kernel<<<dim3(1, 4, 128), 256>>>();
    out_mma_kernel<<<dim3(8, 32), 256>>>(bo, out);
}

// round 13
// speedup vs baseline: 1.4689x; 1.0877x over previous
#include <cuda_runtime.h>
#include <cuda_bf16.h>
#include <cstdint>

typedef __nv_bfloat16 bf16;

#define EMBED 1024
#define TT 512
#define SS 512
#define BATCH 8
#define NHB 128
#define MROWS 4096

// ---------------- scratch (static device globals; no allocation allowed) ----
__device__ bf16 g_q_h[MROWS*EMBED],  g_q_l[MROWS*EMBED];
__device__ bf16 g_k_h[MROWS*EMBED],  g_k_l[MROWS*EMBED];
__device__ bf16 g_v_h[MROWS*EMBED],  g_v_l[MROWS*EMBED];
__device__ bf16 g_Wq_h[EMBED*EMBED], g_Wq_l[EMBED*EMBED];
__device__ bf16 g_Wk_h[EMBED*EMBED], g_Wk_l[EMBED*EMBED];
__device__ bf16 g_Wv_h[EMBED*EMBED], g_Wv_l[EMBED*EMBED];
__device__ bf16 g_Wo_h[EMBED*EMBED], g_Wo_l[EMBED*EMBED];
__device__ bf16 g_qp_h [NHB*TT*64],  g_qp_l [NHB*TT*64];   // [n][t][d]
__device__ bf16 g_kpT_h[NHB*64*SS],  g_kpT_l[NHB*64*SS];   // [n][d][s]
__device__ bf16 g_vp_h [NHB*SS*64],  g_vp_l [NHB*SS*64];   // [n][s][d]
__device__ float g_p [NHB*TT*SS];                          // p_choose (fp32)
__device__ bf16 g_al_h[NHB*TT*SS],   g_al_l[NHB*TT*SS];    // alpha [n][t][s]
__device__ bf16 g_at_h[MROWS*EMBED], g_at_l[MROWS*EMBED];  // merged [t*8+b][h*64+d]

// ============================================================================
// PTX helpers
// ============================================================================
__device__ __forceinline__ uint32_t smem_u32(const void* p) {
    uint32_t a;
    asm("{ .reg .u64 t; cvta.to.shared.u64 t, %1; cvt.u32.u64 %0, t; }"
        : "=r"(a) : "l"(p));
    return a;
}
__device__ __forceinline__ void ldmA(uint32_t r[4], uint32_t addr) {
    asm volatile("ldmatrix.sync.aligned.m8n8.x4.shared.b16 {%0,%1,%2,%3},[%4];"
        : "=r"(r[0]), "=r"(r[1]), "=r"(r[2]), "=r"(r[3]) : "r"(addr));
}
__device__ __forceinline__ void ldmBT(uint32_t r[4], uint32_t addr) {
    asm volatile("ldmatrix.sync.aligned.m8n8.x4.trans.shared.b16 {%0,%1,%2,%3},[%4];"
        : "=r"(r[0]), "=r"(r[1]), "=r"(r[2]), "=r"(r[3]) : "r"(addr));
}
__device__ __forceinline__ void mma16816(float c[4], const uint32_t a[4],
                                         uint32_t b0, uint32_t b1) {
    asm volatile(
        "mma.sync.aligned.m16n8k16.row.col.f32.bf16.bf16.f32 "
        "{%0,%1,%2,%3},{%4,%5,%6,%7},{%8,%9},{%0,%1,%2,%3};"
        : "+f"(c[0]), "+f"(c[1]), "+f"(c[2]), "+f"(c[3])
        : "r"(a[0]), "r"(a[1]), "r"(a[2]), "r"(a[3]), "r"(b0), "r"(b1));
}
__device__ __forceinline__ void cp16(uint32_t dst, const void* src) {
    asm volatile("cp.async.ca.shared.global [%0], [%1], 16;"
        :: "r"(dst), "l"(src));
}
__device__ __forceinline__ void cp_commit() {
    asm volatile("cp.async.commit_group;");
}
template<int N>
__device__ __forceinline__ void cp_wait() {
    asm volatile("cp.async.wait_group %0;" :: "n"(N));
}
__device__ __forceinline__ bf16 tobf(float v) { return __float2bfloat16(v); }

// ============================================================================
// bf16x3 GEMM core (R6 config): 2-stage cp.async, static smem (2 CTA/SM),
// fragment reuse, precomputed shared addresses.
// ============================================================================
template<int BN>
__device__ __forceinline__ void gemm_core(
    const bf16* __restrict__ Ah, long loA, int lda,
    const bf16* __restrict__ Bh, long loB, int ldb,
    int K, float acc[2][BN/16][4])
{
    constexpr int NT = BN / 16;
    constexpr int BSTR = BN + 40;
    constexpr int ASZ = 2 * 128 * 40;
    constexpr int BSZ = 2 * 32 * BSTR;
    constexpr uint32_t ALOb = 128 * 40 * 2;
    constexpr uint32_t BLOb = 32 * BSTR * 2;
    constexpr uint32_t ASTb = ASZ * 2;
    constexpr uint32_t BSTb = BSZ * 2;
    __shared__ bf16 sA[2 * ASZ];
    __shared__ bf16 sB[2 * BSZ];
    const int tid = threadIdx.x;
    const int lane = tid & 31, wid = tid >> 5;
    const int wm = wid & 3, wn = wid >> 2;
    const int nTiles = K / 32;
    const uint32_t sAu = smem_u32(sA), sBu = smem_u32(sB);

    const int aR = tid >> 2, aC = (tid & 3) * 8;
    const int aR2 = aR + 64;
    const bf16* srcA0 = Ah + aR * lda + aC;
    const bf16* srcA1 = Ah + aR2 * lda + aC;
    const uint32_t dA0 = sAu + (uint32_t)(aR * 40 + aC) * 2;
    const uint32_t dA1 = sAu + (uint32_t)(aR2 * 40 + aC) * 2;
    constexpr int BCH = (BN / 8) * 32 / 256;
    const bf16* srcB[BCH];
    uint32_t dB[BCH];
#pragma unroll
    for (int i = 0; i < BCH; i++) {
        int id = tid + i * 256;
        int rr = id / (BN / 8), cc = (id % (BN / 8)) * 8;
        srcB[i] = Bh + rr * ldb + cc;
        dB[i] = sBu + (uint32_t)(rr * BSTR + cc) * 2;
    }

    uint32_t bAddr[NT / 2];
#pragma unroll
    for (int np = 0; np < NT / 2; np++)
        bAddr[np] = sBu + (uint32_t)((lane & 15) * BSTR +
                     wn * (NT * 8) + np * 16 + ((lane >> 4) << 3)) * 2;
    uint32_t aAddr[2];
#pragma unroll
    for (int mt = 0; mt < 2; mt++)
        aAddr[mt] = sAu + (uint32_t)((wm * 32 + mt * 16 + (lane & 15)) * 40 +
                     ((lane >> 4) << 3)) * 2;

    auto loadTile = [&](uint32_t stA, uint32_t stB) {
        cp16(dA0 + stA, srcA0);  cp16(dA0 + ALOb + stA, srcA0 + loA);
        cp16(dA1 + stA, srcA1);  cp16(dA1 + ALOb + stA, srcA1 + loA);
        srcA0 += 32; srcA1 += 32;
#pragma unroll
        for (int i = 0; i < BCH; i++) {
            cp16(dB[i] + stB, srcB[i]);
            cp16(dB[i] + BLOb + stB, srcB[i] + loB);
            srcB[i] += 32 * ldb;
        }
    };

    loadTile(0, 0);
    cp_commit();

    for (int i = 0; i < nTiles; i++) {
        if (i + 1 < nTiles) {
            loadTile(((i + 1) & 1) ? ASTb : 0u, ((i + 1) & 1) ? BSTb : 0u);
            cp_commit();
            cp_wait<1>();
        } else {
            cp_wait<0>();
        }
        __syncthreads();

        const uint32_t stA = (i & 1) ? ASTb : 0u;
        const uint32_t stB = (i & 1) ? BSTb : 0u;
#pragma unroll
        for (int kk = 0; kk < 2; kk++) {
            const uint32_t kA = stA + (kk ? 32u : 0u);
            const uint32_t kB = stB + (kk ? 16u * BSTR * 2u : 0u);
            uint32_t bh[NT][2];
#pragma unroll
            for (int np = 0; np < NT / 2; np++) {
                uint32_t rr[4];
                ldmBT(rr, bAddr[np] + kB);
                bh[2 * np][0] = rr[0]; bh[2 * np][1] = rr[1];
                bh[2 * np + 1][0] = rr[2]; bh[2 * np + 1][1] = rr[3];
            }
            uint32_t ah[2][4], al[2][4];
#pragma unroll
            for (int mt = 0; mt < 2; mt++) {
                ldmA(ah[mt], aAddr[mt] + kA);
                ldmA(al[mt], aAddr[mt] + ALOb + kA);
            }
#pragma unroll
            for (int mt = 0; mt < 2; mt++)
#pragma unroll
                for (int nt = 0; nt < NT; nt++) {
                    mma16816(acc[mt][nt], ah[mt], bh[nt][0], bh[nt][1]);
                    mma16816(acc[mt][nt], al[mt], bh[nt][0], bh[nt][1]);
                }
#pragma unroll
            for (int np = 0; np < NT / 2; np++) {
                uint32_t rr[4];
                ldmBT(rr, bAddr[np] + BLOb + kB);
#pragma unroll
                for (int mt = 0; mt < 2; mt++) {
                    mma16816(acc[mt][2 * np],     ah[mt], rr[0], rr[1]);
                    mma16816(acc[mt][2 * np + 1], ah[mt], rr[2], rr[3]);
                }
            }
        }
        __syncthreads();
    }
}

#define EPI_ROW(mt, r)     (wm * 32 + (mt) * 16 + (lane >> 2) + (((r) >> 1) << 3))
#define EPI_COL(nt, r, NT) (wn * ((NT) * 8) + (nt) * 8 + ((lane & 3) << 1) + ((r) & 1))

// ============================================================================
// split kernels: fp32 -> (bf16 hi, bf16 lo), 4 elems/thread, vectorized.
// ============================================================================
__device__ __forceinline__ void split4(const float* __restrict__ x,
                                       bf16* __restrict__ h,
                                       bf16* __restrict__ l, int i)
{
    float4 v = *(const float4*)&x[i];
    bf16 h0 = tobf(v.x), h1 = tobf(v.y), h2 = tobf(v.z), h3 = tobf(v.w);
    __nv_bfloat162 H01, H23, L01, L23;
    H01.x = h0; H01.y = h1; H23.x = h2; H23.y = h3;
    L01.x = tobf(v.x - __bfloat162float(h0));
    L01.y = tobf(v.y - __bfloat162float(h1));
    L23.x = tobf(v.z - __bfloat162float(h2));
    L23.y = tobf(v.w - __bfloat162float(h3));
    uint2 H, L;
    H.x = *(uint32_t*)&H01; H.y = *(uint32_t*)&H23;
    L.x = *(uint32_t*)&L01; L.y = *(uint32_t*)&L23;
    *(uint2*)&h[i] = H;
    *(uint2*)&l[i] = L;
}

__global__ void split_act_kernel(const float* __restrict__ q,
                                 const float* __restrict__ k,
                                 const float* __restrict__ v)
{
    const float* x; bf16 *h, *l;
    switch (blockIdx.y) {
        case 0:  x = q; h = g_q_h; l = g_q_l; break;
        case 1:  x = k; h = g_k_h; l = g_k_l; break;
        default: x = v; h = g_v_h; l = g_v_l; break;
    }
    int i = (blockIdx.x * blockDim.x + threadIdx.x) * 4;
    split4(x, h, l, i);
}

__global__ void split_w_kernel(const float* __restrict__ Wq,
                               const float* __restrict__ Wk,
                               const float* __restrict__ Wv,
                               const float* __restrict__ Wo)
{
    const float* x; bf16 *h, *l;
    switch (blockIdx.y) {
        case 0:  x = Wq; h = g_Wq_h; l = g_Wq_l; break;
        case 1:  x = Wk; h = g_Wk_h; l = g_Wk_l; break;
        case 2:  x = Wv; h = g_Wv_h; l = g_Wv_l; break;
        default: x = Wo; h = g_Wo_h; l = g_Wo_l; break;
    }
    int i = (blockIdx.x * blockDim.x + threadIdx.x) * 4;
    split4(x, h, l, i);
}

// ============================================================================
// Projection GEMM: which = blockIdx.z + which_base (0=Q,1=K,2=V).
// ============================================================================
__global__ __launch_bounds__(256, 2) void proj_mma_kernel(int which_base)
{
    const int which = blockIdx.z + which_base;
    const bf16 *Ah, *Wh;
    long loA, loW;
    if (which == 0)      { Ah = g_q_h; loA = g_q_l - g_q_h; Wh = g_Wq_h; loW = g_Wq_l - g_Wq_h; }
    else if (which == 1) { Ah = g_k_h; loA = g_k_l - g_k_h; Wh = g_Wk_h; loW = g_Wk_l - g_Wk_h; }
    else                 { Ah = g_v_h; loA = g_v_l - g_v_h; Wh = g_Wv_h; loW = g_Wv_l - g_Wv_h; }
    const float scale = (which == 0) ? 0.125f : 1.0f;

    const int bm = blockIdx.y * 128, bn = blockIdx.x * 128;
    float acc[2][8][4];
#pragma unroll
    for (int i = 0; i < 2; i++)
#pragma unroll
        for (int j = 0; j < 8; j++)
#pragma unroll
            for (int r = 0; r < 4; r++) acc[i][j][r] = 0.f;

    gemm_core<128>(Ah + bm * 1024, loA, 1024, Wh + bn, loW, 1024, 1024, acc);

    const int lane = threadIdx.x & 31, wid = threadIdx.x >> 5;
    const int wm = wid & 3, wn = wid >> 2;
    bf16 *dh, *dl;
    if (which == 0)      { dh = g_qp_h;  dl = g_qp_l;  }
    else if (which == 1) { dh = g_kpT_h; dl = g_kpT_l; }
    else                 { dh = g_vp_h;  dl = g_vp_l;  }

    if (which == 1) {
#pragma unroll
        for (int mt = 0; mt < 2; mt++)
#pragma unroll
            for (int nt = 0; nt < 8; nt++)
#pragma unroll
                for (int r = 0; r < 4; r++) {
                    int row = bm + EPI_ROW(mt, r);
                    int col = bn + EPI_COL(nt, r, 8);
                    int t = row >> 3, b = row & 7;
                    int h = col >> 6, d = col & 63;
                    int n = b * 16 + h;
                    float v = acc[mt][nt][r];
                    int idx = (n * 64 + d) * 512 + t;
                    bf16 hv = tobf(v);
                    dh[idx] = hv;
                    dl[idx] = tobf(v - __bfloat162float(hv));
                }
    } else {
#pragma unroll
        for (int mt = 0; mt < 2; mt++)
#pragma unroll
            for (int nt = 0; nt < 8; nt++)
#pragma unroll
                for (int r2 = 0; r2 < 4; r2 += 2) {
                    int row = bm + EPI_ROW(mt, r2);
                    int col = bn + EPI_COL(nt, r2, 8);   // even
                    int t = row >> 3, b = row & 7;
                    int h = col >> 6, d = col & 63;
                    int n = b * 16 + h;
                    int idx = (n * 512 + t) * 64 + d;
                    float v0 = acc[mt][nt][r2] * scale;
                    float v1 = acc[mt][nt][r2 + 1] * scale;
                    bf16 h0 = tobf(v0), h1 = tobf(v1);
                    __nv_bfloat162 hp; hp.x = h0; hp.y = h1;
                    __nv_bfloat162 lp;
                    lp.x = tobf(v0 - __bfloat162float(h0));
                    lp.y = tobf(v1 - __bfloat162float(h1));
                    *(__nv_bfloat162*)&dh[idx] = hp;
                    *(__nv_bfloat162*)&dl[idx] = lp;
                }
    }
}

// ============================================================================
// Energy + sigmoid -> g_p (fp32)
// ============================================================================
__global__ __launch_bounds__(256, 2) void energy_mma_kernel(const float* __restrict__ ebias)
{
    const int n = blockIdx.z;
    const int t0 = blockIdx.y * 128, s0 = blockIdx.x * 128;
    float acc[2][8][4];
#pragma unroll
    for (int i = 0; i < 2; i++)
#pragma unroll
        for (int j = 0; j < 8; j++)
#pragma unroll
            for (int r = 0; r < 4; r++) acc[i][j][r] = 0.f;

    gemm_core<128>(g_qp_h + n * 512 * 64 + t0 * 64, g_qp_l - g_qp_h, 64,
                   g_kpT_h + n * 64 * 512 + s0,     g_kpT_l - g_kpT_h, 512,
                   64, acc);

    const int lane = threadIdx.x & 31, wid = threadIdx.x >> 5;
    const int wm = wid & 3, wn = wid >> 2;
    const float eb = ebias[0];
#pragma unroll
    for (int mt = 0; mt < 2; mt++)
#pragma unroll
        for (int nt = 0; nt < 8; nt++)
#pragma unroll
            for (int r2 = 0; r2 < 4; r2 += 2) {
                int t = t0 + EPI_ROW(mt, r2);
                int s = s0 + EPI_COL(nt, r2, 8);
                float e0 = acc[mt][nt][r2] + eb;
                float e1 = acc[mt][nt][r2 + 1] + eb;
                float2 pv;
                pv.x = 1.f / (1.f + __expf(-e0));
                pv.y = 1.f / (1.f + __expf(-e1));
                *(float2*)&g_p[(n * 512 + t) * 512 + s] = pv;
            }
}

// ============================================================================
// Fused recurrence — ONE WARP per head, 16 s-elements/lane, no barriers.
// This round: (a) g_p prefetch depth 2 (row t+1 and t+2 held in regs; step t
// issues the load for row t+3), (b) reciprocals of cl computed when cl is
// produced (previous step tail) so the sum chain is a pure FFMA chain.
// grid = 128 blocks (one warp each).
// ============================================================================
__device__ __forceinline__ void ld_row16(float dst[16], const float* __restrict__ src)
{
#pragma unroll
    for (int q4 = 0; q4 < 4; q4++) {
        float4 v = *(const float4*)&src[q4 * 4];
        dst[q4 * 4 + 0] = v.x; dst[q4 * 4 + 1] = v.y;
        dst[q4 * 4 + 2] = v.z; dst[q4 * 4 + 3] = v.w;
    }
}

__global__ __launch_bounds__(32) void recurrence_kernel()
{
    const int lane = threadIdx.x;
    const int n = blockIdx.x;
    const long base = (long)n * (512 * 512) + lane * 16;

    float ap[16], pc[16], rcl[16];

    // ---- prologue: exclusive cumprod of (1-p) for row 0 ----
    {
        float pr[16];
        ld_row16(pr, &g_p[base]);
        float lp[16];
        lp[0] = 1.f - pr[0];
#pragma unroll
        for (int j = 1; j < 16; j++) lp[j] = lp[j - 1] * (1.f - pr[j]);
        float V = lp[15];
#pragma unroll
        for (int o = 1; o < 32; o <<= 1) {
            float vv = __shfl_up_sync(0xffffffffu, V, o);
            if (lane >= o) V *= vv;
        }
        float Vex = __shfl_up_sync(0xffffffffu, V, 1);
        if (lane == 0) Vex = 1.f;
        float ex = Vex;
#pragma unroll
        for (int j = 0; j < 16; j++) {
            float c = fminf(fmaxf(ex, 1e-6f), 1.f);
            rcl[j] = __fdividef(1.f, c);
            pc[j] = pr[j] * ex;
            ex = Vex * lp[j];
        }
    }
#pragma unroll
    for (int j = 0; j < 16; j++) ap[j] = 0.f;
    if (lane == 0) ap[0] = 1.f;

    // ---- prefetch rows 1 and 2 ----
    float pnA[16], pnB[16];
    ld_row16(pnA, &g_p[base + 512]);
    ld_row16(pnB, &g_p[base + 1024]);

    for (int t = 0; t < 512; t++) {
        // issue load for row t+3 (consumed 2 steps from now)
        float pnC[16];
        if (t < 509) {
            ld_row16(pnC, &g_p[base + (long)(t + 3) * 512]);
        } else {
#pragma unroll
            for (int j = 0; j < 16; j++) pnC[j] = 0.f;
        }

        float pn[16];
        if (t < 511) {
#pragma unroll
            for (int j = 0; j < 16; j++) pn[j] = pnA[j];
        } else {
#pragma unroll
            for (int j = 0; j < 16; j++) pn[j] = 0.f;
        }

        // ---- local inclusive prefix sum of ap * rcl (pure FFMA chain) ----
        float ls[16];
        ls[0] = ap[0] * rcl[0];
#pragma unroll
        for (int j = 1; j < 16; j++)
            ls[j] = fmaf(ap[j], rcl[j], ls[j - 1]);

        // ---- local inclusive prefix product of (1 - pnext) ----
        float lp[16];
        lp[0] = 1.f - pn[0];
#pragma unroll
        for (int j = 1; j < 16; j++) lp[j] = lp[j - 1] * (1.f - pn[j]);

        // ---- interleaved warp scans over lane totals ----
        float U = ls[15], V = lp[15];
#pragma unroll
        for (int o = 1; o < 32; o <<= 1) {
            float uu = __shfl_up_sync(0xffffffffu, U, o);
            float vv = __shfl_up_sync(0xffffffffu, V, o);
            if (lane >= o) { U += uu; V *= vv; }
        }
        float Uex = __shfl_up_sync(0xffffffffu, U, 1);
        float Vex = __shfl_up_sync(0xffffffffu, V, 1);
        if (lane == 0) { Uex = 0.f; Vex = 1.f; }

        // ---- alpha row t ----
        float araw[16];
#pragma unroll
        for (int j = 0; j < 16; j++)
            araw[j] = fminf(fmaxf(pc[j] * (Uex + ls[j]), 0.f), 1.f);

        // ---- mass total over s < 511 ----
        float m = 0.f;
#pragma unroll
        for (int j = 0; j < 16; j++) m += araw[j];
        if (lane == 31) m -= araw[15];
#pragma unroll
        for (int o = 16; o > 0; o >>= 1)
            m += __shfl_xor_sync(0xffffffffu, m, o);

        // ---- next-row exclusive cumprod -> rcl/pc for step t+1 ----
        {
            float ex = Vex;
#pragma unroll
            for (int j = 0; j < 16; j++) {
                float c = fminf(fmaxf(ex, 1e-6f), 1.f);
                rcl[j] = __fdividef(1.f, c);
                pc[j] = pn[j] * ex;
                ex = Vex * lp[j];
            }
        }

        // ---- store row t (lane 31's last element mass-fixed) ----
        {
            float v15 = araw[15];
            if (lane == 31) v15 = 1.f - fminf(fmaxf(m, 0.f), 1.f);
            uint4 H, L;
            uint32_t hw[8], lw[8];
#pragma unroll
            for (int j2 = 0; j2 < 8; j2++) {
                float v0 = (j2 * 2 == 15) ? v15 : araw[j2 * 2];
                float v1 = (j2 * 2 + 1 == 15) ? v15 : araw[j2 * 2 + 1];
                __nv_bfloat162 hp, lpp;
                hp.x = tobf(v0); hp.y = tobf(v1);
                lpp.x = tobf(v0 - __bfloat162float(hp.x));
                lpp.y = tobf(v1 - __bfloat162float(hp.y));
                hw[j2] = *(uint32_t*)&hp;
                lw[j2] = *(uint32_t*)&lpp;
            }
            H.x = hw[0]; H.y = hw[1]; H.z = hw[2]; H.w = hw[3];
            L.x = lw[0]; L.y = lw[1]; L.z = lw[2]; L.w = lw[3];
            *(uint4*)&g_al_h[base + (long)t * 512] = H;
            *(uint4*)&g_al_l[base + (long)t * 512] = L;
            H.x = hw[4]; H.y = hw[5]; H.z = hw[6]; H.w = hw[7];
            L.x = lw[4]; L.y = lw[5]; L.z = lw[6]; L.w = lw[7];
            *(uint4*)&g_al_h[base + (long)t * 512 + 8] = H;
            *(uint4*)&g_al_l[base + (long)t * 512 + 8] = L;
        }

        // carry RAW clipped alpha; rotate prefetch buffers
#pragma unroll
        for (int j = 0; j < 16; j++) { ap[j] = araw[j]; pnA[j] = pnB[j]; pnB[j] = pnC[j]; }
    }
}

// ============================================================================
// attn = alpha @ vp  (per n: [512x512]@[512x64]) -> merged hi/lo.
// ============================================================================
__global__ __launch_bounds__(256, 2) void attnv_mma_kernel()
{
    const int n = blockIdx.z;
    const int t0 = blockIdx.y * 128;
    float acc[2][4][4];
#pragma unroll
    for (int i = 0; i < 2; i++)
#pragma unroll
        for (int j = 0; j < 4; j++)
#pragma unroll
            for (int r = 0; r < 4; r++) acc[i][j][r] = 0.f;

    gemm_core<64>(g_al_h + n * 512 * 512 + t0 * 512, g_al_l - g_al_h, 512,
                  g_vp_h + n * 512 * 64,             g_vp_l - g_vp_h, 64,
                  512, acc);

    const int lane = threadIdx.x & 31, wid = threadIdx.x >> 5;
    const int wm = wid & 3, wn = wid >> 2;
    const int b = n >> 4, h = n & 15;
#pragma unroll
    for (int mt = 0; mt < 2; mt++)
#pragma unroll
        for (int nt = 0; nt < 4; nt++)
#pragma unroll
            for (int r2 = 0; r2 < 4; r2 += 2) {
                int t = t0 + EPI_ROW(mt, r2);
                int d = EPI_COL(nt, r2, 4);
                int idx = (t * 8 + b) * 1024 + h * 64 + d;
                float v0 = acc[mt][nt][r2], v1 = acc[mt][nt][r2 + 1];
                bf16 h0 = tobf(v0), h1 = tobf(v1);
                __nv_bfloat162 hp; hp.x = h0; hp.y = h1;
                __nv_bfloat162 lp;
                lp.x = tobf(v0 - __bfloat162float(h0));
                lp.y = tobf(v1 - __bfloat162float(h1));
                *(__nv_bfloat162*)&g_at_h[idx] = hp;
                *(__nv_bfloat162*)&g_at_l[idx] = lp;
            }
}

// ============================================================================
// Output projection: out = attn[4096x1024] @ Wo + bo (fp32 out)
// ============================================================================
__global__ __launch_bounds__(256, 2) void out_mma_kernel(
    const float* __restrict__ bias, float* __restrict__ out)
{
    const int bm = blockIdx.y * 128, bn = blockIdx.x * 128;
    float acc[2][8][4];
#pragma unroll
    for (int i = 0; i < 2; i++)
#pragma unroll
        for (int j = 0; j < 8; j++)
#pragma unroll
            for (int r = 0; r < 4; r++) acc[i][j][r] = 0.f;

    gemm_core<128>(g_at_h + bm * 1024, g_at_l - g_at_h, 1024,
                   g_Wo_h + bn,        g_Wo_l - g_Wo_h, 1024, 1024, acc);

    const int lane = threadIdx.x & 31, wid = threadIdx.x >> 5;
    const int wm = wid & 3, wn = wid >> 2;
#pragma unroll
    for (int mt = 0; mt < 2; mt++)
#pragma unroll
        for (int nt = 0; nt < 8; nt++)
#pragma unroll
            for (int r2 = 0; r2 < 4; r2 += 2) {
                int row = bm + EPI_ROW(mt, r2);
                int col = bn + EPI_COL(nt, r2, 8);
                float2 ov;
                ov.x = acc[mt][nt][r2]     + bias[col];
                ov.y = acc[mt][nt][r2 + 1] + bias[col + 1];
                *(float2*)&out[row * 1024 + col] = ov;
            }
}

// ============================================================================
extern "C" void kernel_launch(void* const* d_in, const int* in_sizes, int n_in,
                              void* d_out, int out_size)
{
    const float* q  = (const float*)d_in[0];
    const float* k  = (const float*)d_in[1];
    const float* v  = (const float*)d_in[2];
    const float* Wq = (const float*)d_in[3];
    const float* Wk = (const float*)d_in[4];
    const float* Wv = (const float*)d_in[5];
    const float* Wo = (const float*)d_in[6];
    const float* bo = (const float*)d_in[7];
    const float* eb = (const float*)d_in[8];
    float* out = (float*)d_out;

    cudaStream_t s2;
    cudaStreamCreateWithFlags(&s2, cudaStreamNonBlocking);
    cudaEvent_t e1, e2;
    cudaEventCreateWithFlags(&e1, cudaEventDisableTiming);
    cudaEventCreateWithFlags(&e2, cudaEventDisableTiming);

    split_act_kernel<<<dim3(MROWS * EMBED / 1024, 3), 256>>>(q, k, v);
    split_w_kernel<<<dim3(EMBED * EMBED / 1024, 4), 256>>>(Wq, Wk, Wv, Wo);

    cudaEventRecord(e1, 0);
    cudaStreamWaitEvent(s2, e1, 0);

    proj_mma_kernel<<<dim3(8, 32, 2), 256>>>(0);          // Q, K  (stream 0)
    proj_mma_kernel<<<dim3(8, 32, 1), 256, 0, s2>>>(2);   // V     (stream s2)
    cudaEventRecord(e2, s2);

    energy_mma_kernel<<<dim3(4, 4, 128), 256>>>(eb);
    recurrence_kernel<<<128, 32>>>();

    cudaStreamWaitEvent(0, e2, 0);                        // join V before attnv
    attnv_mma_kernel<<<dim3(1, 4, 128), 256>>>();
    out_mma_kernel<<<dim3(8, 32), 256>>>(bo, out);
}

// round 15
// speedup vs baseline: 1.6719x; 1.1382x over previous
#include <cuda_runtime.h>
#include <cuda_bf16.h>
#include <cstdint>

typedef __nv_bfloat16 bf16;

#define EMBED 1024
#define TT 512
#define SS 512
#define BATCH 8
#define NHB 128
#define MROWS 4096

// ---------------- scratch (static device globals; no allocation allowed) ----
__device__ bf16 g_q_h[MROWS*EMBED],  g_q_l[MROWS*EMBED];
__device__ bf16 g_k_h[MROWS*EMBED],  g_k_l[MROWS*EMBED];
__device__ bf16 g_v_h[MROWS*EMBED],  g_v_l[MROWS*EMBED];
__device__ bf16 g_Wq_h[EMBED*EMBED], g_Wq_l[EMBED*EMBED];
__device__ bf16 g_Wk_h[EMBED*EMBED], g_Wk_l[EMBED*EMBED];
__device__ bf16 g_Wv_h[EMBED*EMBED], g_Wv_l[EMBED*EMBED];
__device__ bf16 g_Wo_h[EMBED*EMBED], g_Wo_l[EMBED*EMBED];
__device__ bf16 g_qp_h [NHB*TT*64],  g_qp_l [NHB*TT*64];   // [n][t][d]
__device__ bf16 g_kpT_h[NHB*64*SS],  g_kpT_l[NHB*64*SS];   // [n][d][s]
__device__ bf16 g_vp_h [NHB*SS*64],  g_vp_l [NHB*SS*64];   // [n][s][d]
__device__ float g_p [NHB*TT*SS + 4*SS];                   // p_choose + pad rows
__device__ bf16 g_al_h[NHB*TT*SS],   g_al_l[NHB*TT*SS];    // alpha [n][t][s]
__device__ bf16 g_at_h[MROWS*EMBED], g_at_l[MROWS*EMBED];  // merged [t*8+b][h*64+d]

// ============================================================================
// PTX helpers
// ============================================================================
__device__ __forceinline__ uint32_t smem_u32(const void* p) {
    uint32_t a;
    asm("{ .reg .u64 t; cvta.to.shared.u64 t, %1; cvt.u32.u64 %0, t; }"
        : "=r"(a) : "l"(p));
    return a;
}
__device__ __forceinline__ void ldmA(uint32_t r[4], uint32_t addr) {
    asm volatile("ldmatrix.sync.aligned.m8n8.x4.shared.b16 {%0,%1,%2,%3},[%4];"
        : "=r"(r[0]), "=r"(r[1]), "=r"(r[2]), "=r"(r[3]) : "r"(addr));
}
__device__ __forceinline__ void ldmBT(uint32_t r[4], uint32_t addr) {
    asm volatile("ldmatrix.sync.aligned.m8n8.x4.trans.shared.b16 {%0,%1,%2,%3},[%4];"
        : "=r"(r[0]), "=r"(r[1]), "=r"(r[2]), "=r"(r[3]) : "r"(addr));
}
__device__ __forceinline__ void mma16816(float c[4], const uint32_t a[4],
                                         uint32_t b0, uint32_t b1) {
    asm volatile(
        "mma.sync.aligned.m16n8k16.row.col.f32.bf16.bf16.f32 "
        "{%0,%1,%2,%3},{%4,%5,%6,%7},{%8,%9},{%0,%1,%2,%3};"
        : "+f"(c[0]), "+f"(c[1]), "+f"(c[2]), "+f"(c[3])
        : "r"(a[0]), "r"(a[1]), "r"(a[2]), "r"(a[3]), "r"(b0), "r"(b1));
}
__device__ __forceinline__ void cp16(uint32_t dst, const void* src) {
    asm volatile("cp.async.ca.shared.global [%0], [%1], 16;"
        :: "r"(dst), "l"(src));
}
__device__ __forceinline__ void cp_commit() {
    asm volatile("cp.async.commit_group;");
}
template<int N>
__device__ __forceinline__ void cp_wait() {
    asm volatile("cp.async.wait_group %0;" :: "n"(N));
}
__device__ __forceinline__ bf16 tobf(float v) { return __float2bfloat16(v); }

// ============================================================================
// bf16x3 GEMM core (unchanged)
// ============================================================================
template<int BN>
__device__ __forceinline__ void gemm_core(
    const bf16* __restrict__ Ah, long loA, int lda,
    const bf16* __restrict__ Bh, long loB, int ldb,
    int K, float acc[2][BN/16][4])
{
    constexpr int NT = BN / 16;
    constexpr int BSTR = BN + 40;
    constexpr int ASZ = 2 * 128 * 40;
    constexpr int BSZ = 2 * 32 * BSTR;
    constexpr uint32_t ALOb = 128 * 40 * 2;
    constexpr uint32_t BLOb = 32 * BSTR * 2;
    constexpr uint32_t ASTb = ASZ * 2;
    constexpr uint32_t BSTb = BSZ * 2;
    __shared__ bf16 sA[2 * ASZ];
    __shared__ bf16 sB[2 * BSZ];
    const int tid = threadIdx.x;
    const int lane = tid & 31, wid = tid >> 5;
    const int wm = wid & 3, wn = wid >> 2;
    const int nTiles = K / 32;
    const uint32_t sAu = smem_u32(sA), sBu = smem_u32(sB);

    const int aR = tid >> 2, aC = (tid & 3) * 8;
    const int aR2 = aR + 64;
    const bf16* srcA0 = Ah + aR * lda + aC;
    const bf16* srcA1 = Ah + aR2 * lda + aC;
    const uint32_t dA0 = sAu + (uint32_t)(aR * 40 + aC) * 2;
    const uint32_t dA1 = sAu + (uint32_t)(aR2 * 40 + aC) * 2;
    constexpr int BCH = (BN / 8) * 32 / 256;
    const bf16* srcB[BCH];
    uint32_t dB[BCH];
#pragma unroll
    for (int i = 0; i < BCH; i++) {
        int id = tid + i * 256;
        int rr = id / (BN / 8), cc = (id % (BN / 8)) * 8;
        srcB[i] = Bh + rr * ldb + cc;
        dB[i] = sBu + (uint32_t)(rr * BSTR + cc) * 2;
    }

    uint32_t bAddr[NT / 2];
#pragma unroll
    for (int np = 0; np < NT / 2; np++)
        bAddr[np] = sBu + (uint32_t)((lane & 15) * BSTR +
                     wn * (NT * 8) + np * 16 + ((lane >> 4) << 3)) * 2;
    uint32_t aAddr[2];
#pragma unroll
    for (int mt = 0; mt < 2; mt++)
        aAddr[mt] = sAu + (uint32_t)((wm * 32 + mt * 16 + (lane & 15)) * 40 +
                     ((lane >> 4) << 3)) * 2;

    auto loadTile = [&](uint32_t stA, uint32_t stB) {
        cp16(dA0 + stA, srcA0);  cp16(dA0 + ALOb + stA, srcA0 + loA);
        cp16(dA1 + stA, srcA1);  cp16(dA1 + ALOb + stA, srcA1 + loA);
        srcA0 += 32; srcA1 += 32;
#pragma unroll
        for (int i = 0; i < BCH; i++) {
            cp16(dB[i] + stB, srcB[i]);
            cp16(dB[i] + BLOb + stB, srcB[i] + loB);
            srcB[i] += 32 * ldb;
        }
    };

    loadTile(0, 0);
    cp_commit();

    for (int i = 0; i < nTiles; i++) {
        if (i + 1 < nTiles) {
            loadTile(((i + 1) & 1) ? ASTb : 0u, ((i + 1) & 1) ? BSTb : 0u);
            cp_commit();
            cp_wait<1>();
        } else {
            cp_wait<0>();
        }
        __syncthreads();

        const uint32_t stA = (i & 1) ? ASTb : 0u;
        const uint32_t stB = (i & 1) ? BSTb : 0u;
#pragma unroll
        for (int kk = 0; kk < 2; kk++) {
            const uint32_t kA = stA + (kk ? 32u : 0u);
            const uint32_t kB = stB + (kk ? 16u * BSTR * 2u : 0u);
            uint32_t bh[NT][2];
#pragma unroll
            for (int np = 0; np < NT / 2; np++) {
                uint32_t rr[4];
                ldmBT(rr, bAddr[np] + kB);
                bh[2 * np][0] = rr[0]; bh[2 * np][1] = rr[1];
                bh[2 * np + 1][0] = rr[2]; bh[2 * np + 1][1] = rr[3];
            }
            uint32_t ah[2][4], al[2][4];
#pragma unroll
            for (int mt = 0; mt < 2; mt++) {
                ldmA(ah[mt], aAddr[mt] + kA);
                ldmA(al[mt], aAddr[mt] + ALOb + kA);
            }
#pragma unroll
            for (int mt = 0; mt < 2; mt++)
#pragma unroll
                for (int nt = 0; nt < NT; nt++) {
                    mma16816(acc[mt][nt], ah[mt], bh[nt][0], bh[nt][1]);
                    mma16816(acc[mt][nt], al[mt], bh[nt][0], bh[nt][1]);
                }
#pragma unroll
            for (int np = 0; np < NT / 2; np++) {
                uint32_t rr[4];
                ldmBT(rr, bAddr[np] + BLOb + kB);
#pragma unroll
                for (int mt = 0; mt < 2; mt++) {
                    mma16816(acc[mt][2 * np],     ah[mt], rr[0], rr[1]);
                    mma16816(acc[mt][2 * np + 1], ah[mt], rr[2], rr[3]);
                }
            }
        }
        __syncthreads();
    }
}

#define EPI_ROW(mt, r)     (wm * 32 + (mt) * 16 + (lane >> 2) + (((r) >> 1) << 3))
#define EPI_COL(nt, r, NT) (wn * ((NT) * 8) + (nt) * 8 + ((lane & 3) << 1) + ((r) & 1))

// ============================================================================
// split kernels
// ============================================================================
__device__ __forceinline__ void split4(const float* __restrict__ x,
                                       bf16* __restrict__ h,
                                       bf16* __restrict__ l, int i)
{
    float4 v = *(const float4*)&x[i];
    bf16 h0 = tobf(v.x), h1 = tobf(v.y), h2 = tobf(v.z), h3 = tobf(v.w);
    __nv_bfloat162 H01, H23, L01, L23;
    H01.x = h0; H01.y = h1; H23.x = h2; H23.y = h3;
    L01.x = tobf(v.x - __bfloat162float(h0));
    L01.y = tobf(v.y - __bfloat162float(h1));
    L23.x = tobf(v.z - __bfloat162float(h2));
    L23.y = tobf(v.w - __bfloat162float(h3));
    uint2 H, L;
    H.x = *(uint32_t*)&H01; H.y = *(uint32_t*)&H23;
    L.x = *(uint32_t*)&L01; L.y = *(uint32_t*)&L23;
    *(uint2*)&h[i] = H;
    *(uint2*)&l[i] = L;
}

__global__ void split_act_kernel(const float* __restrict__ q,
                                 const float* __restrict__ k,
                                 const float* __restrict__ v)
{
    const float* x; bf16 *h, *l;
    switch (blockIdx.y) {
        case 0:  x = q; h = g_q_h; l = g_q_l; break;
        case 1:  x = k; h = g_k_h; l = g_k_l; break;
        default: x = v; h = g_v_h; l = g_v_l; break;
    }
    int i = (blockIdx.x * blockDim.x + threadIdx.x) * 4;
    split4(x, h, l, i);
}

__global__ void split_w_kernel(const float* __restrict__ Wq,
                               const float* __restrict__ Wk,
                               const float* __restrict__ Wv,
                               const float* __restrict__ Wo)
{
    const float* x; bf16 *h, *l;
    switch (blockIdx.y) {
        case 0:  x = Wq; h = g_Wq_h; l = g_Wq_l; break;
        case 1:  x = Wk; h = g_Wk_h; l = g_Wk_l; break;
        case 2:  x = Wv; h = g_Wv_h; l = g_Wv_l; break;
        default: x = Wo; h = g_Wo_h; l = g_Wo_l; break;
    }
    int i = (blockIdx.x * blockDim.x + threadIdx.x) * 4;
    split4(x, h, l, i);
}

// ============================================================================
// Projection GEMM: which = blockIdx.z + which_base (0=Q,1=K,2=V).
// ============================================================================
__global__ __launch_bounds__(256, 2) void proj_mma_kernel(int which_base)
{
    const int which = blockIdx.z + which_base;
    const bf16 *Ah, *Wh;
    long loA, loW;
    if (which == 0)      { Ah = g_q_h; loA = g_q_l - g_q_h; Wh = g_Wq_h; loW = g_Wq_l - g_Wq_h; }
    else if (which == 1) { Ah = g_k_h; loA = g_k_l - g_k_h; Wh = g_Wk_h; loW = g_Wk_l - g_Wk_h; }
    else                 { Ah = g_v_h; loA = g_v_l - g_v_h; Wh = g_Wv_h; loW = g_Wv_l - g_Wv_h; }
    const float scale = (which == 0) ? 0.125f : 1.0f;

    const int bm = blockIdx.y * 128, bn = blockIdx.x * 128;
    float acc[2][8][4];
#pragma unroll
    for (int i = 0; i < 2; i++)
#pragma unroll
        for (int j = 0; j < 8; j++)
#pragma unroll
            for (int r = 0; r < 4; r++) acc[i][j][r] = 0.f;

    gemm_core<128>(Ah + bm * 1024, loA, 1024, Wh + bn, loW, 1024, 1024, acc);

    const int lane = threadIdx.x & 31, wid = threadIdx.x >> 5;
    const int wm = wid & 3, wn = wid >> 2;
    bf16 *dh, *dl;
    if (which == 0)      { dh = g_qp_h;  dl = g_qp_l;  }
    else if (which == 1) { dh = g_kpT_h; dl = g_kpT_l; }
    else                 { dh = g_vp_h;  dl = g_vp_l;  }

    if (which == 1) {
#pragma unroll
        for (int mt = 0; mt < 2; mt++)
#pragma unroll
            for (int nt = 0; nt < 8; nt++)
#pragma unroll
                for (int r = 0; r < 4; r++) {
                    int row = bm + EPI_ROW(mt, r);
                    int col = bn + EPI_COL(nt, r, 8);
                    int t = row >> 3, b = row & 7;
                    int h = col >> 6, d = col & 63;
                    int n = b * 16 + h;
                    float v = acc[mt][nt][r];
                    int idx = (n * 64 + d) * 512 + t;
                    bf16 hv = tobf(v);
                    dh[idx] = hv;
                    dl[idx] = tobf(v - __bfloat162float(hv));
                }
    } else {
#pragma unroll
        for (int mt = 0; mt < 2; mt++)
#pragma unroll
            for (int nt = 0; nt < 8; nt++)
#pragma unroll
                for (int r2 = 0; r2 < 4; r2 += 2) {
                    int row = bm + EPI_ROW(mt, r2);
                    int col = bn + EPI_COL(nt, r2, 8);   // even
                    int t = row >> 3, b = row & 7;
                    int h = col >> 6, d = col & 63;
                    int n = b * 16 + h;
                    int idx = (n * 512 + t) * 64 + d;
                    float v0 = acc[mt][nt][r2] * scale;
                    float v1 = acc[mt][nt][r2 + 1] * scale;
                    bf16 h0 = tobf(v0), h1 = tobf(v1);
                    __nv_bfloat162 hp; hp.x = h0; hp.y = h1;
                    __nv_bfloat162 lp;
                    lp.x = tobf(v0 - __bfloat162float(h0));
                    lp.y = tobf(v1 - __bfloat162float(h1));
                    *(__nv_bfloat162*)&dh[idx] = hp;
                    *(__nv_bfloat162*)&dl[idx] = lp;
                }
    }
}

// ============================================================================
// Energy + sigmoid -> g_p (fp32)
// ============================================================================
__global__ __launch_bounds__(256, 2) void energy_mma_kernel(const float* __restrict__ ebias)
{
    const int n = blockIdx.z;
    const int t0 = blockIdx.y * 128, s0 = blockIdx.x * 128;
    float acc[2][8][4];
#pragma unroll
    for (int i = 0; i < 2; i++)
#pragma unroll
        for (int j = 0; j < 8; j++)
#pragma unroll
            for (int r = 0; r < 4; r++) acc[i][j][r] = 0.f;

    gemm_core<128>(g_qp_h + n * 512 * 64 + t0 * 64, g_qp_l - g_qp_h, 64,
                   g_kpT_h + n * 64 * 512 + s0,     g_kpT_l - g_kpT_h, 512,
                   64, acc);

    const int lane = threadIdx.x & 31, wid = threadIdx.x >> 5;
    const int wm = wid & 3, wn = wid >> 2;
    const float eb = ebias[0];
#pragma unroll
    for (int mt = 0; mt < 2; mt++)
#pragma unroll
        for (int nt = 0; nt < 8; nt++)
#pragma unroll
            for (int r2 = 0; r2 < 4; r2 += 2) {
                int t = t0 + EPI_ROW(mt, r2);
                int s = s0 + EPI_COL(nt, r2, 8);
                float e0 = acc[mt][nt][r2] + eb;
                float e1 = acc[mt][nt][r2 + 1] + eb;
                float2 pv;
                pv.x = 1.f / (1.f + __expf(-e0));
                pv.y = 1.f / (1.f + __expf(-e1));
                *(float2*)&g_p[(n * 512 + t) * 512 + s] = pv;
            }
}

// ============================================================================
// Fused recurrence — ONE WARP per head, no barriers, 3-buffer rotation:
// step t consumes buffer (t%3) holding row t+1 and, after its last use,
// reloads it with row t+4 (≈2.5 steps of latency cover, zero copies).
// araw written in place into ap.  Tail (t>=504) peeled with direct loads.
// ============================================================================
__device__ __forceinline__ void ld_row16(float dst[16], const float* __restrict__ src)
{
#pragma unroll
    for (int q4 = 0; q4 < 4; q4++) {
        float4 v = *(const float4*)&src[q4 * 4];
        dst[q4 * 4 + 0] = v.x; dst[q4 * 4 + 1] = v.y;
        dst[q4 * 4 + 2] = v.z; dst[q4 * 4 + 3] = v.w;
    }
}

__device__ __forceinline__ void rec_step(
    int t, long base, int lane,
    float ap[16], float pc[16], float rcl[16], float pn[16], bool doLoad)
{
    // local prefix sum of ap*rcl (pure FFMA chain)
    float ls[16];
    ls[0] = ap[0] * rcl[0];
#pragma unroll
    for (int j = 1; j < 16; j++) ls[j] = fmaf(ap[j], rcl[j], ls[j - 1]);

    // local prefix product of (1 - pn)
    float lp[16];
    lp[0] = 1.f - pn[0];
#pragma unroll
    for (int j = 1; j < 16; j++) lp[j] = lp[j - 1] * (1.f - pn[j]);

    // interleaved warp scans
    float U = ls[15], V = lp[15];
#pragma unroll
    for (int o = 1; o < 32; o <<= 1) {
        float uu = __shfl_up_sync(0xffffffffu, U, o);
        float vv = __shfl_up_sync(0xffffffffu, V, o);
        if (lane >= o) { U += uu; V *= vv; }
    }
    float Uex = __shfl_up_sync(0xffffffffu, U, 1);
    float Vex = __shfl_up_sync(0xffffffffu, V, 1);
    if (lane == 0) { Uex = 0.f; Vex = 1.f; }

    // alpha row t, written in place into ap
#pragma unroll
    for (int j = 0; j < 16; j++)
        ap[j] = fminf(fmaxf(pc[j] * (Uex + ls[j]), 0.f), 1.f);

    // mass total over s < 511
    float m = 0.f;
#pragma unroll
    for (int j = 0; j < 16; j++) m += ap[j];
    if (lane == 31) m -= ap[15];
#pragma unroll
    for (int o = 16; o > 0; o >>= 1)
        m += __shfl_xor_sync(0xffffffffu, m, o);

    // next-row exclusive cumprod -> rcl/pc for step t+1 (pn's last use)
    {
        float ex = Vex;
#pragma unroll
        for (int j = 0; j < 16; j++) {
            float c = fminf(fmaxf(ex, 1e-6f), 1.f);
            rcl[j] = __fdividef(1.f, c);
            pc[j] = pn[j] * ex;
            ex = Vex * lp[j];
        }
    }

    // reload this buffer with row t+4 (consumed at step t+3) — true prefetch
    if (doLoad) ld_row16(pn, &g_p[base + (long)(t + 4) * 512]);

    // store row t (lane 31's last element mass-fixed; RAW ap carries on)
    {
        float v15 = ap[15];
        if (lane == 31) v15 = 1.f - fminf(fmaxf(m, 0.f), 1.f);
        uint32_t hw[8], lw[8];
#pragma unroll
        for (int j2 = 0; j2 < 8; j2++) {
            float v0 = ap[j2 * 2];
            float v1 = (j2 == 7) ? v15 : ap[j2 * 2 + 1];
            __nv_bfloat162 hp, lpp;
            hp.x = tobf(v0); hp.y = tobf(v1);
            lpp.x = tobf(v0 - __bfloat162float(hp.x));
            lpp.y = tobf(v1 - __bfloat162float(hp.y));
            hw[j2] = *(uint32_t*)&hp;
            lw[j2] = *(uint32_t*)&lpp;
        }
        uint4 H, L;
        H.x = hw[0]; H.y = hw[1]; H.z = hw[2]; H.w = hw[3];
        L.x = lw[0]; L.y = lw[1]; L.z = lw[2]; L.w = lw[3];
        *(uint4*)&g_al_h[base + (long)t * 512] = H;
        *(uint4*)&g_al_l[base + (long)t * 512] = L;
        H.x = hw[4]; H.y = hw[5]; H.z = hw[6]; H.w = hw[7];
        L.x = lw[4]; L.y = lw[5]; L.z = lw[6]; L.w = lw[7];
        *(uint4*)&g_al_h[base + (long)t * 512 + 8] = H;
        *(uint4*)&g_al_l[base + (long)t * 512 + 8] = L;
    }
}

__global__ __launch_bounds__(32) void recurrence_kernel()
{
    const int lane = threadIdx.x;
    const int n = blockIdx.x;
    const long base = (long)n * (512 * 512) + lane * 16;

    float ap[16], pc[16], rcl[16];

    // ---- prologue: exclusive cumprod of (1-p) for row 0 ----
    {
        float pr[16];
        ld_row16(pr, &g_p[base]);
        float lp[16];
        lp[0] = 1.f - pr[0];
#pragma unroll
        for (int j = 1; j < 16; j++) lp[j] = lp[j - 1] * (1.f - pr[j]);
        float V = lp[15];
#pragma unroll
        for (int o = 1; o < 32; o <<= 1) {
            float vv = __shfl_up_sync(0xffffffffu, V, o);
            if (lane >= o) V *= vv;
        }
        float Vex = __shfl_up_sync(0xffffffffu, V, 1);
        if (lane == 0) Vex = 1.f;
        float ex = Vex;
#pragma unroll
        for (int j = 0; j < 16; j++) {
            float c = fminf(fmaxf(ex, 1e-6f), 1.f);
            rcl[j] = __fdividef(1.f, c);
            pc[j] = pr[j] * ex;
            ex = Vex * lp[j];
        }
    }
#pragma unroll
    for (int j = 0; j < 16; j++) ap[j] = 0.f;
    if (lane == 0) ap[0] = 1.f;

    // ---- 3 rotating buffers: b0=row1, b1=row2, b2=row3 ----
    float b0[16], b1[16], b2[16];
    ld_row16(b0, &g_p[base + 1 * 512]);
    ld_row16(b1, &g_p[base + 2 * 512]);
    ld_row16(b2, &g_p[base + 3 * 512]);

    // main loop: t in [0, 504), unroll 3, no copies (max prefetch row 507)
    for (int t = 0; t < 504; t += 3) {
        rec_step(t,     base, lane, ap, pc, rcl, b0, true);
        rec_step(t + 1, base, lane, ap, pc, rcl, b1, true);
        rec_step(t + 2, base, lane, ap, pc, rcl, b2, true);
    }

    // tail: t = 504..511.  After the loop b0=row505, b1=row506, b2=row507.
    for (int t = 504; t < 512; t++) {
        float pn[16];
        if (t == 504) { for (int j = 0; j < 16; j++) pn[j] = b0[j]; }
        else if (t == 505) { for (int j = 0; j < 16; j++) pn[j] = b1[j]; }
        else if (t == 506) { for (int j = 0; j < 16; j++) pn[j] = b2[j]; }
        else if (t < 511) ld_row16(pn, &g_p[base + (long)(t + 1) * 512]);
        else { for (int j = 0; j < 16; j++) pn[j] = 0.f; }
        rec_step(t, base, lane, ap, pc, rcl, pn, false);
    }
}

// ============================================================================
// attn = alpha @ vp  (per n: [512x512]@[512x64]) -> merged hi/lo.
// ============================================================================
__global__ __launch_bounds__(256, 2) void attnv_mma_kernel()
{
    const int n = blockIdx.z;
    const int t0 = blockIdx.y * 128;
    float acc[2][4][4];
#pragma unroll
    for (int i = 0; i < 2; i++)
#pragma unroll
        for (int j = 0; j < 4; j++)
#pragma unroll
            for (int r = 0; r < 4; r++) acc[i][j][r] = 0.f;

    gemm_core<64>(g_al_h + n * 512 * 512 + t0 * 512, g_al_l - g_al_h, 512,
                  g_vp_h + n * 512 * 64,             g_vp_l - g_vp_h, 64,
                  512, acc);

    const int lane = threadIdx.x & 31, wid = threadIdx.x >> 5;
    const int wm = wid & 3, wn = wid >> 2;
    const int b = n >> 4, h = n & 15;
#pragma unroll
    for (int mt = 0; mt < 2; mt++)
#pragma unroll
        for (int nt = 0; nt < 4; nt++)
#pragma unroll
            for (int r2 = 0; r2 < 4; r2 += 2) {
                int t = t0 + EPI_ROW(mt, r2);
                int d = EPI_COL(nt, r2, 4);
                int idx = (t * 8 + b) * 1024 + h * 64 + d;
                float v0 = acc[mt][nt][r2], v1 = acc[mt][nt][r2 + 1];
                bf16 h0 = tobf(v0), h1 = tobf(v1);
                __nv_bfloat162 hp; hp.x = h0; hp.y = h1;
                __nv_bfloat162 lp;
                lp.x = tobf(v0 - __bfloat162float(h0));
                lp.y = tobf(v1 - __bfloat162float(h1));
                *(__nv_bfloat162*)&g_at_h[idx] = hp;
                *(__nv_bfloat162*)&g_at_l[idx] = lp;
            }
}

// ============================================================================
// Output projection: out = attn[4096x1024] @ Wo + bo (fp32 out)
// ============================================================================
__global__ __launch_bounds__(256, 2) void out_mma_kernel(
    const float* __restrict__ bias, float* __restrict__ out)
{
    const int bm = blockIdx.y * 128, bn = blockIdx.x * 128;
    float acc[2][8][4];
#pragma unroll
    for (int i = 0; i < 2; i++)
#pragma unroll
        for (int j = 0; j < 8; j++)
#pragma unroll
            for (int r = 0; r < 4; r++) acc[i][j][r] = 0.f;

    gemm_core<128>(g_at_h + bm * 1024, g_at_l - g_at_h, 1024,
                   g_Wo_h + bn,        g_Wo_l - g_Wo_h, 1024, 1024, acc);

    const int lane = threadIdx.x & 31, wid = threadIdx.x >> 5;
    const int wm = wid & 3, wn = wid >> 2;
#pragma unroll
    for (int mt = 0; mt < 2; mt++)
#pragma unroll
        for (int nt = 0; nt < 8; nt++)
#pragma unroll
            for (int r2 = 0; r2 < 4; r2 += 2) {
                int row = bm + EPI_ROW(mt, r2);
                int col = bn + EPI_COL(nt, r2, 8);
                float2 ov;
                ov.x = acc[mt][nt][r2]     + bias[col];
                ov.y = acc[mt][nt][r2 + 1] + bias[col + 1];
                *(float2*)&out[row * 1024 + col] = ov;
            }
}

// ============================================================================
extern "C" void kernel_launch(void* const* d_in, const int* in_sizes, int n_in,
                              void* d_out, int out_size)
{
    const float* q  = (const float*)d_in[0];
    const float* k  = (const float*)d_in[1];
    const float* v  = (const float*)d_in[2];
    const float* Wq = (const float*)d_in[3];
    const float* Wk = (const float*)d_in[4];
    const float* Wv = (const float*)d_in[5];
    const float* Wo = (const float*)d_in[6];
    const float* bo = (const float*)d_in[7];
    const float* eb = (const float*)d_in[8];
    float* out = (float*)d_out;

    // resources created ONCE, on the (uncaptured) correctness call — nothing
    // is created or destroyed during graph capture or replay.
    static cudaStream_t s2 = nullptr;
    static cudaEvent_t e1, e2;
    if (!s2) {
        cudaStreamCreateWithFlags(&s2, cudaStreamNonBlocking);
        cudaEventCreateWithFlags(&e1, cudaEventDisableTiming);
        cudaEventCreateWithFlags(&e2, cudaEventDisableTiming);
    }

    split_act_kernel<<<dim3(MROWS * EMBED / 1024, 3), 256>>>(q, k, v);
    split_w_kernel<<<dim3(EMBED * EMBED / 1024, 4), 256>>>(Wq, Wk, Wv, Wo);

    cudaEventRecord(e1, 0);
    cudaStreamWaitEvent(s2, e1, 0);

    proj_mma_kernel<<<dim3(8, 32, 2), 256>>>(0);          // Q, K  (stream 0)
    proj_mma_kernel<<<dim3(8, 32, 1), 256, 0, s2>>>(2);   // V     (stream s2)
    cudaEventRecord(e2, s2);

    energy_mma_kernel<<<dim3(4, 4, 128), 256>>>(eb);
    recurrence_kernel<<<128, 32>>>();

    cudaStreamWaitEvent(0, e2, 0);                        // join V before attnv
    attnv_mma_kernel<<<dim3(1, 4, 128), 256>>>();
    out_mma_kernel<<<dim3(8, 32), 256>>>(bo, out);
}